// round 4
// baseline (speedup 1.0000x reference)
#include <cuda_runtime.h>
#include <cuda_bf16.h>
#include <math.h>
#include <stdint.h>

#define BATCH   32768
#define D_IN    512
#define D_DENSE 256
#define TSTEPS  16
#define FEAT    16
#define H1      128
#define H2      32
#define NCLS    10

// ---------------- state: row-major, bf16 hi/lo pairs ----------------
__device__ __nv_bfloat16 g_acthi[BATCH * D_DENSE], g_actlo[BATCH * D_DENSE];
__device__ __nv_bfloat16 g_h1hi[2][BATCH * H1],    g_h1lo[2][BATCH * H1];
__device__ __nv_bfloat16 g_h2hi[2][BATCH * H2],    g_h2lo[2][BATCH * H2];
__device__ float g_c1[BATCH * H1], g_c2[BATCH * H2];

// prepacked weights: row n (gate-interleaved), cols [hi(K)|lo(K)] bf16
__device__ __nv_bfloat16 g_Wp1[(4 * H1) * 2 * (FEAT + H1)];  // [512][288]
__device__ __nv_bfloat16 g_Wp2[(4 * H2) * 2 * (H1 + H2)];    // [128][320]
__device__ __nv_bfloat16 g_WpD[D_DENSE * 2 * D_IN];          // [256][1024], panel-major
__device__ float g_bc1[4 * H1], g_bc2[4 * H2];
__device__ float g_d1sc[D_DENSE], g_d1sh[D_DENSE];

// ---------------- helpers ----------------
__device__ __forceinline__ uint32_t smem_u32(const void* p) {
    uint32_t a;
    asm("{ .reg .u64 t; cvta.to.shared.u64 t, %1; cvt.u32.u64 %0, t; }" : "=r"(a) : "l"(p));
    return a;
}
__device__ __forceinline__ float ftanh(float x) {
    float y;
    asm("tanh.approx.f32 %0, %1;" : "=f"(y) : "f"(x));
    return y;
}
__device__ __forceinline__ float fsigm(float x) { return 0.5f * ftanh(0.5f * x) + 0.5f; }

__device__ __forceinline__ void ldsm4(uint32_t* r, uint32_t addr) {
    asm volatile("ldmatrix.sync.aligned.m8n8.x4.shared.b16 {%0,%1,%2,%3}, [%4];"
                 : "=r"(r[0]), "=r"(r[1]), "=r"(r[2]), "=r"(r[3]) : "r"(addr));
}
__device__ __forceinline__ void mma16816(float* d, const uint32_t* a, uint32_t b0, uint32_t b1) {
    asm volatile(
        "mma.sync.aligned.m16n8k16.row.col.f32.bf16.bf16.f32 "
        "{%0,%1,%2,%3}, {%4,%5,%6,%7}, {%8,%9}, {%0,%1,%2,%3};"
        : "+f"(d[0]), "+f"(d[1]), "+f"(d[2]), "+f"(d[3])
        : "r"(a[0]), "r"(a[1]), "r"(a[2]), "r"(a[3]), "r"(b0), "r"(b1));
}

// warp GEMM: 3-term (AhBh + AlBh + AhBl), warp tile 32(M) x 64(N), K per term.
// A smem [128][S] bf16 (hi cols 0..K-1, lo K..2K-1), B smem [128][S] same.
template <int K, int S>
__device__ __forceinline__ void warp_gemm3(uint32_t Asm, uint32_t Bsm,
                                           int wm, int wn, int lane, float acc[2][8][4]) {
    const uint32_t abase = Asm + ((((uint32_t)(wm * 32 + (lane & 15))) * S + ((lane >> 4) << 3)) << 1);
    const uint32_t bbase = Bsm + ((((uint32_t)(wn * 64 + ((lane >> 4) << 3) + (lane & 7))) * S
                                   + (((lane >> 3) & 1) << 3)) << 1);
#pragma unroll
    for (int term = 0; term < 3; term++) {
        const int ao = (term == 1) ? K : 0;
        const int bo = (term == 2) ? K : 0;
#pragma unroll
        for (int c = 0; c < K / 16; c++) {
            uint32_t a0[4], a1[4], b[4][4];
            ldsm4(a0, abase + ((ao + c * 16) << 1));
            ldsm4(a1, abase + ((16 * S + ao + c * 16) << 1));
#pragma unroll
            for (int nj = 0; nj < 4; nj++)
                ldsm4(b[nj], bbase + (((nj * 16) * S + bo + c * 16) << 1));
#pragma unroll
            for (int mi = 0; mi < 2; mi++) {
                const uint32_t* A = mi ? a1 : a0;
#pragma unroll
                for (int nj = 0; nj < 4; nj++) {
                    mma16816(acc[mi][2 * nj], A, b[nj][0], b[nj][1]);
                    mma16816(acc[mi][2 * nj + 1], A, b[nj][2], b[nj][3]);
                }
            }
        }
    }
}

// ---------------- init & prepack ----------------
__global__ void init_state_kernel() {
    int idx = blockIdx.x * blockDim.x + threadIdx.x;
    int stride = gridDim.x * blockDim.x;
    const __nv_bfloat16 z = __float2bfloat16(0.f);
    for (int i = idx; i < BATCH * H1; i += stride) {
        g_h1hi[0][i] = z; g_h1lo[0][i] = z; g_c1[i] = 0.f;
    }
    for (int i = idx; i < BATCH * H2; i += stride) {
        g_h2hi[0][i] = z; g_h2lo[0][i] = z; g_c2[i] = 0.f;
    }
}

__global__ void prepack_kernel(const float* __restrict__ Wx1, const float* __restrict__ Wh1,
                               const float* __restrict__ b1,
                               const float* __restrict__ Wx2, const float* __restrict__ Wh2,
                               const float* __restrict__ b2,
                               const float* __restrict__ W_d1, const float* __restrict__ b_d1,
                               const float* __restrict__ gamma, const float* __restrict__ beta,
                               const float* __restrict__ mean, const float* __restrict__ var) {
    int idx = blockIdx.x * blockDim.x + threadIdx.x;
    int stride = gridDim.x * blockDim.x;
    {
        constexpr int K = FEAT + H1;
        for (int i = idx; i < 4 * H1 * K; i += stride) {
            int n = i / K, k = i % K;
            int u = n >> 2, g = n & 3, src = g * H1 + u;
            float w = (k < FEAT) ? Wx1[k * 4 * H1 + src] : Wh1[(k - FEAT) * 4 * H1 + src];
            __nv_bfloat16 hi = __float2bfloat16(w);
            g_Wp1[(size_t)n * 2 * K + k] = hi;
            g_Wp1[(size_t)n * 2 * K + K + k] = __float2bfloat16(w - __bfloat162float(hi));
        }
        for (int i = idx; i < 4 * H1; i += stride) {
            int u = i >> 2, g = i & 3;
            g_bc1[i] = b1[g * H1 + u];
        }
    }
    {
        constexpr int K = H1 + H2;
        for (int i = idx; i < 4 * H2 * K; i += stride) {
            int n = i / K, k = i % K;
            int u = n >> 2, g = n & 3, src = g * H2 + u;
            float w = (k < H1) ? Wx2[k * 4 * H2 + src] : Wh2[(k - H1) * 4 * H2 + src];
            __nv_bfloat16 hi = __float2bfloat16(w);
            g_Wp2[(size_t)n * 2 * K + k] = hi;
            g_Wp2[(size_t)n * 2 * K + K + k] = __float2bfloat16(w - __bfloat162float(hi));
        }
        for (int i = idx; i < 4 * H2; i += stride) {
            int u = i >> 2, g = i & 3;
            g_bc2[i] = b2[g * H2 + u];
        }
    }
    // Dense1 weights: panel-major [n][p*256 + {hi 0..127 | lo 128..255}], p = k>>7
    for (int i = idx; i < D_DENSE * D_IN; i += stride) {
        int n = i / D_IN, k = i % D_IN;
        int p = k >> 7, kk = k & 127;
        float w = W_d1[(size_t)k * D_DENSE + n];
        __nv_bfloat16 hi = __float2bfloat16(w);
        g_WpD[(size_t)n * 1024 + p * 256 + kk] = hi;
        g_WpD[(size_t)n * 1024 + p * 256 + 128 + kk] = __float2bfloat16(w - __bfloat162float(hi));
    }
    for (int i = idx; i < D_DENSE; i += stride) {
        float sc = gamma[i] * rsqrtf(var[i] + 1e-3f);
        g_d1sc[i] = sc;
        g_d1sh[i] = beta[i] + (b_d1[i] - mean[i]) * sc;
    }
}

// ---------------- Dense1: x[B,512] fp32 -> act bf16 hi/lo (BN + leaky fused) ----------------
__global__ __launch_bounds__(256, 1) void dense1_kernel(const float* __restrict__ x) {
    constexpr int KP = 128;          // K per panel
    constexpr int S = 2 * KP + 8;    // 264, (S/8)=33 odd
    extern __shared__ char smem[];
    const uint32_t Asm = smem_u32(smem);
    const uint32_t Bsm = Asm + 128 * S * 2;
    char* const Bc = smem + 128 * S * 2;
    const int tid = threadIdx.x;
    const int lane = tid & 31, wid = tid >> 5;
    const int wm = wid & 3, wn = wid >> 2;
    const int m0 = blockIdx.x * 128, n0 = blockIdx.y * 128;

    float acc[2][8][4] = {};
    for (int p = 0; p < 4; p++) {
        // A: convert fp32 -> hi/lo bf16
        for (int task = tid; task < 128 * 16; task += 256) {
            const int r = task >> 4, o = task & 15;
            const float* src = x + (size_t)(m0 + r) * D_IN + p * KP + o * 8;
            const float4 v0 = *(const float4*)src;
            const float4 v1 = *(const float4*)(src + 4);
            __nv_bfloat16 h[8], l[8];
            const float vv[8] = {v0.x, v0.y, v0.z, v0.w, v1.x, v1.y, v1.z, v1.w};
#pragma unroll
            for (int i = 0; i < 8; i++) {
                h[i] = __float2bfloat16(vv[i]);
                l[i] = __float2bfloat16(vv[i] - __bfloat162float(h[i]));
            }
            *(uint4*)(smem + ((size_t)r * S + o * 8) * 2) = *(uint4*)h;
            *(uint4*)(smem + ((size_t)r * S + KP + o * 8) * 2) = *(uint4*)l;
        }
        // B: straight copy from prepacked panel
        for (int task = tid; task < 128 * 32; task += 256) {
            const int n = task >> 5, o = task & 31;
            const uint4 v = *(const uint4*)(g_WpD + (size_t)(n0 + n) * 1024 + p * 256 + o * 8);
            *(uint4*)(Bc + ((size_t)n * S + o * 8) * 2) = v;
        }
        __syncthreads();
        warp_gemm3<KP, S>(Asm, Bsm, wm, wn, lane, acc);
        __syncthreads();
    }

    // epilogue: BN + leaky, write bf16 hi/lo row-major
    const int g = lane >> 2;
#pragma unroll
    for (int ni = 0; ni < 8; ni++) {
        const int n = n0 + wn * 64 + ni * 8 + (lane & 3) * 2;
        const float sc0 = g_d1sc[n], sc1 = g_d1sc[n + 1];
        const float sh0 = g_d1sh[n], sh1 = g_d1sh[n + 1];
#pragma unroll
        for (int mi = 0; mi < 2; mi++) {
#pragma unroll
            for (int half = 0; half < 2; half++) {
                const int row = m0 + wm * 32 + mi * 16 + g + half * 8;
                float v0 = acc[mi][ni][half * 2 + 0] * sc0 + sh0;
                float v1 = acc[mi][ni][half * 2 + 1] * sc1 + sh1;
                v0 = (v0 >= 0.f) ? v0 : 0.2f * v0;
                v1 = (v1 >= 0.f) ? v1 : 0.2f * v1;
                __nv_bfloat16 h0 = __float2bfloat16(v0), h1 = __float2bfloat16(v1);
                __nv_bfloat162 hp; hp.x = h0; hp.y = h1;
                __nv_bfloat162 lp;
                lp.x = __float2bfloat16(v0 - __bfloat162float(h0));
                lp.y = __float2bfloat16(v1 - __bfloat162float(h1));
                *(__nv_bfloat162*)(g_acthi + (size_t)row * D_DENSE + n) = hp;
                *(__nv_bfloat162*)(g_actlo + (size_t)row * D_DENSE + n) = lp;
            }
        }
    }
}

// ---------------- fused LSTM step ----------------
template <int KX, int HID>
__global__ __launch_bounds__(256, 1) void lstm_kernel(int t) {
    constexpr int K = KX + HID;
    constexpr int S = 2 * K + 8;     // 296 (37 odd) / 328 (41 odd)
    extern __shared__ char smem[];
    const uint32_t Asm = smem_u32(smem);
    const uint32_t Bsm = Asm + 128 * S * 2;
    char* const Bc = smem + 128 * S * 2;
    const int tid = threadIdx.x;
    const int lane = tid & 31, wid = tid >> 5;
    const int wm = wid & 3, wn = wid >> 2;
    const int m0 = blockIdx.x * 128, n0 = blockIdx.y * 128;
    const int p = t & 1;

    const __nv_bfloat16 *xhi, *xlo, *hhi, *hlo;
    __nv_bfloat16 *hdhi, *hdlo;
    float* cbuf;
    const __nv_bfloat16* W;
    const float* bias;
    int xstride, xoff;
    if (HID == H1) {
        xhi = g_acthi; xlo = g_actlo; xstride = D_DENSE; xoff = t * FEAT;
        hhi = g_h1hi[p]; hlo = g_h1lo[p];
        hdhi = g_h1hi[p ^ 1]; hdlo = g_h1lo[p ^ 1];
        cbuf = g_c1; W = g_Wp1; bias = g_bc1;
    } else {
        xhi = g_h1hi[p ^ 1]; xlo = g_h1lo[p ^ 1]; xstride = H1; xoff = 0;
        hhi = g_h2hi[p]; hlo = g_h2lo[p];
        hdhi = g_h2hi[p ^ 1]; hdlo = g_h2lo[p ^ 1];
        cbuf = g_c2; W = g_Wp2; bias = g_bc2;
    }

    // A copy: [x|h] hi block cols 0..K-1, lo block K..2K-1
    constexpr int OCT = K / 8;
    for (int task = tid; task < 128 * 2 * OCT; task += 256) {
        const int r = task / (2 * OCT);
        const int j = task % (2 * OCT);
        const bool lo = j >= OCT;
        const int o = lo ? j - OCT : j;
        const int col = o * 8;
        uint4 v;
        if (col < KX)
            v = *(const uint4*)((lo ? xlo : xhi) + (size_t)(m0 + r) * xstride + xoff + col);
        else
            v = *(const uint4*)((lo ? hlo : hhi) + (size_t)(m0 + r) * HID + (col - KX));
        *(uint4*)(smem + ((size_t)r * S + (lo ? K : 0) + col) * 2) = v;
    }
    // B copy
    for (int task = tid; task < 128 * (K / 4); task += 256) {
        const int n = task / (K / 4);
        const int o = task % (K / 4);
        const uint4 v = *(const uint4*)(W + (size_t)(n0 + n) * 2 * K + o * 8);
        *(uint4*)(Bc + ((size_t)n * S + o * 8) * 2) = v;
    }
    __syncthreads();

    float acc[2][8][4] = {};
    warp_gemm3<K, S>(Asm, Bsm, wm, wn, lane, acc);

    // epilogue: pair-swap gates, fuse cell update
    const int g = lane >> 2;
    const bool odd = lane & 1;
#pragma unroll
    for (int ni = 0; ni < 8; ni++) {
        const int u = ((n0 + wn * 64 + ni * 8) >> 2) + ((lane & 2) >> 1);
        const float4 bb = *(const float4*)(bias + 4 * u);
#pragma unroll
        for (int mi = 0; mi < 2; mi++) {
            const float d0 = acc[mi][ni][0], d1 = acc[mi][ni][1];
            const float d2 = acc[mi][ni][2], d3 = acc[mi][ni][3];
            const float s0 = __shfl_xor_sync(0xffffffffu, odd ? d0 : d2, 1);
            const float s1 = __shfl_xor_sync(0xffffffffu, odd ? d1 : d3, 1);
            const float zi = (odd ? s0 : d0) + bb.x;
            const float zf = (odd ? s1 : d1) + bb.y;
            const float zg = (odd ? d2 : s0) + bb.z;
            const float zo = (odd ? d3 : s1) + bb.w;
            const int row = m0 + wm * 32 + mi * 16 + g + (odd ? 8 : 0);
            const float ig = fsigm(zi);
            const float fg = fsigm(zf);
            const float gg = ftanh(zg);
            const float og = fsigm(zo);
            const size_t off = (size_t)row * HID + u;
            const float cn = fg * cbuf[off] + ig * gg;
            cbuf[off] = cn;
            const float hv = og * ftanh(cn);
            const __nv_bfloat16 hh = __float2bfloat16(hv);
            hdhi[off] = hh;
            hdlo[off] = __float2bfloat16(hv - __bfloat162float(hh));
        }
    }
}

// ---------------- Dense2 + softmax ----------------
__global__ __launch_bounds__(256) void dense2_softmax_kernel(
    const float* __restrict__ Wd2, const float* __restrict__ bd2, float* __restrict__ out) {
    __shared__ float Ws[H2 * NCLS];
    __shared__ float bs[NCLS];
    int tid = threadIdx.x;
    for (int i = tid; i < H2 * NCLS; i += blockDim.x) Ws[i] = Wd2[i];
    if (tid < NCLS) bs[tid] = bd2[tid];
    __syncthreads();
    int row = blockIdx.x * blockDim.x + tid;
    const __nv_bfloat16* hh = g_h2hi[0] + (size_t)row * H2;  // t=15 writes buffer 0
    const __nv_bfloat16* hl = g_h2lo[0] + (size_t)row * H2;
    float acc[NCLS];
#pragma unroll
    for (int j = 0; j < NCLS; j++) acc[j] = bs[j];
#pragma unroll
    for (int k = 0; k < H2; k++) {
        float xv = __bfloat162float(hh[k]) + __bfloat162float(hl[k]);
#pragma unroll
        for (int j = 0; j < NCLS; j++) acc[j] += xv * Ws[k * NCLS + j];
    }
    float m = acc[0];
#pragma unroll
    for (int j = 1; j < NCLS; j++) m = fmaxf(m, acc[j]);
    float ssum = 0.f;
#pragma unroll
    for (int j = 0; j < NCLS; j++) { acc[j] = expf(acc[j] - m); ssum += acc[j]; }
    float inv = 1.f / ssum;
#pragma unroll
    for (int j = 0; j < NCLS; j++) out[(size_t)row * NCLS + j] = acc[j] * inv;
}

// ---------------- launch ----------------
extern "C" void kernel_launch(void* const* d_in, const int* in_sizes, int n_in,
                              void* d_out, int out_size) {
    const float* x        = (const float*)d_in[0];
    const float* W_d1     = (const float*)d_in[1];
    const float* b_d1     = (const float*)d_in[2];
    const float* bn_gamma = (const float*)d_in[3];
    const float* bn_beta  = (const float*)d_in[4];
    const float* bn_mean  = (const float*)d_in[5];
    const float* bn_var   = (const float*)d_in[6];
    const float* Wx1      = (const float*)d_in[7];
    const float* Wh1      = (const float*)d_in[8];
    const float* b1       = (const float*)d_in[9];
    const float* Wx2      = (const float*)d_in[10];
    const float* Wh2      = (const float*)d_in[11];
    const float* b2       = (const float*)d_in[12];
    const float* W_d2     = (const float*)d_in[13];
    const float* b_d2     = (const float*)d_in[14];
    float* out = (float*)d_out;

    constexpr int S1 = 2 * (FEAT + H1) + 8;   // 296
    constexpr int S2 = 2 * (H1 + H2) + 8;     // 328
    constexpr int SD = 2 * 128 + 8;           // 264
    const int SM1 = 2 * 128 * S1 * 2;         // 151552
    const int SM2 = 2 * 128 * S2 * 2;         // 167936
    const int SMD = 2 * 128 * SD * 2;         // 135168

    cudaFuncSetAttribute(dense1_kernel, cudaFuncAttributeMaxDynamicSharedMemorySize, SMD);
    cudaFuncSetAttribute(lstm_kernel<FEAT, H1>, cudaFuncAttributeMaxDynamicSharedMemorySize, SM1);
    cudaFuncSetAttribute(lstm_kernel<H1, H2>, cudaFuncAttributeMaxDynamicSharedMemorySize, SM2);

    prepack_kernel<<<256, 256>>>(Wx1, Wh1, b1, Wx2, Wh2, b2, W_d1, b_d1,
                                 bn_gamma, bn_beta, bn_mean, bn_var);
    init_state_kernel<<<2048, 256>>>();
    dense1_kernel<<<dim3(BATCH / 128, D_DENSE / 128), 256, SMD>>>(x);
    for (int t = 0; t < TSTEPS; t++) {
        lstm_kernel<FEAT, H1><<<dim3(BATCH / 128, 4 * H1 / 128), 256, SM1>>>(t);
        lstm_kernel<H1, H2><<<dim3(BATCH / 128, 1), 256, SM2>>>(t);
    }
    dense2_softmax_kernel<<<BATCH / 256, 256>>>(W_d2, b_d2, out);
}

// round 5
// speedup vs baseline: 1.6607x; 1.6607x over previous
#include <cuda_runtime.h>
#include <cuda_bf16.h>
#include <math.h>
#include <stdint.h>

#define BATCH   32768
#define D_IN    512
#define D_DENSE 256
#define TSTEPS  16
#define FEAT    16
#define H1      128
#define H2      32
#define NCLS    10

// ---------------- state: row-major, bf16 hi/lo pairs ----------------
__device__ __nv_bfloat16 g_acthi[BATCH * D_DENSE], g_actlo[BATCH * D_DENSE];
__device__ __nv_bfloat16 g_h1hi[2][BATCH * H1],    g_h1lo[2][BATCH * H1];
__device__ __nv_bfloat16 g_h2hi[2][BATCH * H2],    g_h2lo[2][BATCH * H2];
__device__ float g_c1[BATCH * H1], g_c2[BATCH * H2];

// prepacked weights: row n (gate-interleaved), cols [hi(K)|lo(K)] bf16
__device__ __nv_bfloat16 g_Wp1[(4 * H1) * 2 * (FEAT + H1)];  // [512][288]
__device__ __nv_bfloat16 g_Wp2[(4 * H2) * 2 * (H1 + H2)];    // [128][320]
__device__ __nv_bfloat16 g_WpD[D_DENSE * 2 * D_IN];          // [256][1024], panel-major
__device__ float g_bc1[4 * H1], g_bc2[4 * H2];
__device__ float g_d1sc[D_DENSE], g_d1sh[D_DENSE];

// ---------------- helpers ----------------
__device__ __forceinline__ uint32_t smem_u32(const void* p) {
    uint32_t a;
    asm("{ .reg .u64 t; cvta.to.shared.u64 t, %1; cvt.u32.u64 %0, t; }" : "=r"(a) : "l"(p));
    return a;
}
__device__ __forceinline__ float ftanh(float x) {
    float y;
    asm("tanh.approx.f32 %0, %1;" : "=f"(y) : "f"(x));
    return y;
}
__device__ __forceinline__ float fsigm(float x) { return 0.5f * ftanh(0.5f * x) + 0.5f; }

__device__ __forceinline__ void ldsm4(uint32_t* r, uint32_t addr) {
    asm volatile("ldmatrix.sync.aligned.m8n8.x4.shared.b16 {%0,%1,%2,%3}, [%4];"
                 : "=r"(r[0]), "=r"(r[1]), "=r"(r[2]), "=r"(r[3]) : "r"(addr));
}
__device__ __forceinline__ void mma16816(float* d, const uint32_t* a, uint32_t b0, uint32_t b1) {
    asm volatile(
        "mma.sync.aligned.m16n8k16.row.col.f32.bf16.bf16.f32 "
        "{%0,%1,%2,%3}, {%4,%5,%6,%7}, {%8,%9}, {%0,%1,%2,%3};"
        : "+f"(d[0]), "+f"(d[1]), "+f"(d[2]), "+f"(d[3])
        : "r"(a[0]), "r"(a[1]), "r"(a[2]), "r"(a[3]), "r"(b0), "r"(b1));
}
__device__ __forceinline__ void cp16(uint32_t dst, const void* src) {
    asm volatile("cp.async.cg.shared.global [%0], [%1], 16;" :: "r"(dst), "l"(src));
}
#define CP_COMMIT() asm volatile("cp.async.commit_group;" ::: "memory")
#define CP_WAIT(n)  asm volatile("cp.async.wait_group %0;" :: "n"(n) : "memory")

// ================= fused LSTM step body (virtual-K streamed, cp.async 2-stage) ============
// 512 threads, 16 warps 4(M)x4(N), warp tile 32x32, CTA tile 128x128.
template <int KX, int HID, int BK>
__device__ __forceinline__ void lstm_body(int t, int m0, int n0, char* smemc) {
    constexpr int K = KX + HID;
    constexpr int SA = BK + 8;               // halfs per smem row; SA*2/16 odd
    constexpr int STG = 128 * SA * 2;        // bytes per tile
    constexpr int CPT = K / BK;              // chunks per term
    constexpr int NCH = 3 * CPT;             // virtual chunks
    constexpr int GA = BK / 8;               // 16B groups per row
    const int tid = threadIdx.x;
    const int lane = tid & 31, wid = tid >> 5;
    const int wm = wid & 3, wn = wid >> 2;
    const uint32_t sbase = smem_u32(smemc);
    const int p = t & 1;

    const __nv_bfloat16 *xhi, *xlo, *hhi, *hlo;
    __nv_bfloat16 *hdhi, *hdlo;
    float* cbuf;
    const __nv_bfloat16* W;
    const float* bias;
    int xstride, xoff;
    if (HID == H1) {
        xhi = g_acthi; xlo = g_actlo; xstride = D_DENSE; xoff = t * FEAT;
        hhi = g_h1hi[p]; hlo = g_h1lo[p];
        hdhi = g_h1hi[p ^ 1]; hdlo = g_h1lo[p ^ 1];
        cbuf = g_c1; W = g_Wp1; bias = g_bc1;
    } else {
        xhi = g_h1hi[p ^ 1]; xlo = g_h1lo[p ^ 1]; xstride = H1; xoff = 0;
        hhi = g_h2hi[p]; hlo = g_h2lo[p];
        hdhi = g_h2hi[p ^ 1]; hdlo = g_h2lo[p ^ 1];
        cbuf = g_c2; W = g_Wp2; bias = g_bc2;
    }

    auto load_chunk = [&](int c, int s) {
        const int term = c / CPT;
        const int kbase = (c % CPT) * BK;
        const __nv_bfloat16* xa = (term == 1) ? xlo : xhi;
        const __nv_bfloat16* ha = (term == 1) ? hlo : hhi;
        const int bofs = (term == 2) ? K : 0;
        const uint32_t As = sbase + s * 2 * STG;
        const uint32_t Bs = As + STG;
#pragma unroll
        for (int task = tid; task < 128 * GA; task += 512) {
            const int r = task / GA, gg = task % GA;
            const int col = kbase + gg * 8;
            const __nv_bfloat16* src = (col < KX)
                ? xa + (size_t)(m0 + r) * xstride + xoff + col
                : ha + (size_t)(m0 + r) * HID + (col - KX);
            cp16(As + (uint32_t)(r * SA + gg * 8) * 2, src);
        }
#pragma unroll
        for (int task = tid; task < 128 * GA; task += 512) {
            const int n = task / GA, gg = task % GA;
            cp16(Bs + (uint32_t)(n * SA + gg * 8) * 2,
                 W + (size_t)(n0 + n) * (2 * K) + bofs + kbase + gg * 8);
        }
    };

    const uint32_t aoffw = (uint32_t)((wm * 32 + (lane & 15)) * SA + ((lane >> 4) << 3)) * 2;
    const uint32_t boffw = (uint32_t)((wn * 32 + ((lane >> 4) << 3) + (lane & 7)) * SA
                                      + (((lane >> 3) & 1) << 3)) * 2;
    float acc[2][4][4] = {};

    load_chunk(0, 0);
    CP_COMMIT();
#pragma unroll 1
    for (int c = 0; c < NCH; c++) {
        if (c + 1 < NCH) {
            load_chunk(c + 1, (c + 1) & 1);
            CP_COMMIT();
            CP_WAIT(1);
        } else {
            CP_COMMIT();
            CP_WAIT(0);
        }
        __syncthreads();
        const uint32_t As = sbase + (c & 1) * 2 * STG;
        const uint32_t Bs = As + STG;
#pragma unroll
        for (int kk = 0; kk < BK / 16; kk++) {
            uint32_t a0[4], a1[4], bA[4], bB[4];
            ldsm4(a0, As + aoffw + kk * 32);
            ldsm4(a1, As + aoffw + 16 * SA * 2 + kk * 32);
            ldsm4(bA, Bs + boffw + kk * 32);
            ldsm4(bB, Bs + boffw + 16 * SA * 2 + kk * 32);
#pragma unroll
            for (int mi = 0; mi < 2; mi++) {
                const uint32_t* A = mi ? a1 : a0;
                mma16816(acc[mi][0], A, bA[0], bA[1]);
                mma16816(acc[mi][1], A, bA[2], bA[3]);
                mma16816(acc[mi][2], A, bB[0], bB[1]);
                mma16816(acc[mi][3], A, bB[2], bB[3]);
            }
        }
        __syncthreads();
    }

    // epilogue: pair-swap gates, fuse cell update (verified in R4)
    const int g = lane >> 2;
    const bool odd = lane & 1;
#pragma unroll
    for (int ni = 0; ni < 4; ni++) {
        const int u = ((n0 + wn * 32 + ni * 8) >> 2) + ((lane & 2) >> 1);
        const float4 bb = *(const float4*)(bias + 4 * u);
#pragma unroll
        for (int mi = 0; mi < 2; mi++) {
            const float d0 = acc[mi][ni][0], d1 = acc[mi][ni][1];
            const float d2 = acc[mi][ni][2], d3 = acc[mi][ni][3];
            const float s0 = __shfl_xor_sync(0xffffffffu, odd ? d0 : d2, 1);
            const float s1 = __shfl_xor_sync(0xffffffffu, odd ? d1 : d3, 1);
            const float zi = (odd ? s0 : d0) + bb.x;
            const float zf = (odd ? s1 : d1) + bb.y;
            const float zg = (odd ? d2 : s0) + bb.z;
            const float zo = (odd ? d3 : s1) + bb.w;
            const int row = m0 + wm * 32 + mi * 16 + g + (odd ? 8 : 0);
            const float ig = fsigm(zi);
            const float fg = fsigm(zf);
            const float gg = ftanh(zg);
            const float og = fsigm(zo);
            const size_t off = (size_t)row * HID + u;
            const float cn = fg * cbuf[off] + ig * gg;
            cbuf[off] = cn;
            const float hv = og * ftanh(cn);
            const __nv_bfloat16 hh = __float2bfloat16(hv);
            hdhi[off] = hh;
            hdlo[off] = __float2bfloat16(hv - __bfloat162float(hh));
        }
    }
}

__global__ __launch_bounds__(512, 2) void lstm1_first_kernel() {
    extern __shared__ char smem[];
    lstm_body<FEAT, H1, 48>(0, (blockIdx.x & 255) * 128, (blockIdx.x >> 8) * 128, smem);
}

// combined: lstm2(t) on blocks [0,256); lstm1(t+1) on blocks [256,1280)
__global__ __launch_bounds__(512, 2) void step_kernel(int t, int do_l1) {
    extern __shared__ char smem[];
    if (blockIdx.x < 256) {
        lstm_body<H1, H2, 32>(t, blockIdx.x * 128, 0, smem);
    } else if (do_l1) {
        const int bx = blockIdx.x - 256;
        lstm_body<FEAT, H1, 48>(t + 1, (bx & 255) * 128, (bx >> 8) * 128, smem);
    }
}

// ---------------- init & prepack ----------------
__global__ void init_state_kernel() {
    int idx = blockIdx.x * blockDim.x + threadIdx.x;
    int stride = gridDim.x * blockDim.x;
    const __nv_bfloat16 z = __float2bfloat16(0.f);
    for (int i = idx; i < BATCH * H1; i += stride) {
        g_h1hi[0][i] = z; g_h1lo[0][i] = z; g_c1[i] = 0.f;
    }
    for (int i = idx; i < BATCH * H2; i += stride) {
        g_h2hi[0][i] = z; g_h2lo[0][i] = z; g_c2[i] = 0.f;
    }
}

__global__ void prepack_kernel(const float* __restrict__ Wx1, const float* __restrict__ Wh1,
                               const float* __restrict__ b1,
                               const float* __restrict__ Wx2, const float* __restrict__ Wh2,
                               const float* __restrict__ b2,
                               const float* __restrict__ W_d1, const float* __restrict__ b_d1,
                               const float* __restrict__ gamma, const float* __restrict__ beta,
                               const float* __restrict__ mean, const float* __restrict__ var) {
    int idx = blockIdx.x * blockDim.x + threadIdx.x;
    int stride = gridDim.x * blockDim.x;
    {
        constexpr int K = FEAT + H1;
        for (int i = idx; i < 4 * H1 * K; i += stride) {
            int n = i / K, k = i % K;
            int u = n >> 2, g = n & 3, src = g * H1 + u;
            float w = (k < FEAT) ? Wx1[k * 4 * H1 + src] : Wh1[(k - FEAT) * 4 * H1 + src];
            __nv_bfloat16 hi = __float2bfloat16(w);
            g_Wp1[(size_t)n * 2 * K + k] = hi;
            g_Wp1[(size_t)n * 2 * K + K + k] = __float2bfloat16(w - __bfloat162float(hi));
        }
        for (int i = idx; i < 4 * H1; i += stride) {
            int u = i >> 2, g = i & 3;
            g_bc1[i] = b1[g * H1 + u];
        }
    }
    {
        constexpr int K = H1 + H2;
        for (int i = idx; i < 4 * H2 * K; i += stride) {
            int n = i / K, k = i % K;
            int u = n >> 2, g = n & 3, src = g * H2 + u;
            float w = (k < H1) ? Wx2[k * 4 * H2 + src] : Wh2[(k - H1) * 4 * H2 + src];
            __nv_bfloat16 hi = __float2bfloat16(w);
            g_Wp2[(size_t)n * 2 * K + k] = hi;
            g_Wp2[(size_t)n * 2 * K + K + k] = __float2bfloat16(w - __bfloat162float(hi));
        }
        for (int i = idx; i < 4 * H2; i += stride) {
            int u = i >> 2, g = i & 3;
            g_bc2[i] = b2[g * H2 + u];
        }
    }
    // Dense1 weights: panel-major [n][p*256 + {hi 0..127 | lo 128..255}], p = k>>7
    for (int i = idx; i < D_DENSE * D_IN; i += stride) {
        int n = i / D_IN, k = i % D_IN;
        int p = k >> 7, kk = k & 127;
        float w = W_d1[(size_t)k * D_DENSE + n];
        __nv_bfloat16 hi = __float2bfloat16(w);
        g_WpD[(size_t)n * 1024 + p * 256 + kk] = hi;
        g_WpD[(size_t)n * 1024 + p * 256 + 128 + kk] = __float2bfloat16(w - __bfloat162float(hi));
    }
    for (int i = idx; i < D_DENSE; i += stride) {
        float sc = gamma[i] * rsqrtf(var[i] + 1e-3f);
        g_d1sc[i] = sc;
        g_d1sh[i] = beta[i] + (b_d1[i] - mean[i]) * sc;
    }
}

// ---------------- Dense1 (R4, verified): 256 threads, 8 warps 4x2, warp 32x64 ----------------
template <int K, int S>
__device__ __forceinline__ void warp_gemm3(uint32_t Asm, uint32_t Bsm,
                                           int wm, int wn, int lane, float acc[2][8][4]) {
    const uint32_t abase = Asm + ((((uint32_t)(wm * 32 + (lane & 15))) * S + ((lane >> 4) << 3)) << 1);
    const uint32_t bbase = Bsm + ((((uint32_t)(wn * 64 + ((lane >> 4) << 3) + (lane & 7))) * S
                                   + (((lane >> 3) & 1) << 3)) << 1);
#pragma unroll
    for (int term = 0; term < 3; term++) {
        const int ao = (term == 1) ? K : 0;
        const int bo = (term == 2) ? K : 0;
#pragma unroll
        for (int c = 0; c < K / 16; c++) {
            uint32_t a0[4], a1[4], b[4][4];
            ldsm4(a0, abase + ((ao + c * 16) << 1));
            ldsm4(a1, abase + ((16 * S + ao + c * 16) << 1));
#pragma unroll
            for (int nj = 0; nj < 4; nj++)
                ldsm4(b[nj], bbase + (((nj * 16) * S + bo + c * 16) << 1));
#pragma unroll
            for (int mi = 0; mi < 2; mi++) {
                const uint32_t* A = mi ? a1 : a0;
#pragma unroll
                for (int nj = 0; nj < 4; nj++) {
                    mma16816(acc[mi][2 * nj], A, b[nj][0], b[nj][1]);
                    mma16816(acc[mi][2 * nj + 1], A, b[nj][2], b[nj][3]);
                }
            }
        }
    }
}

__global__ __launch_bounds__(256, 1) void dense1_kernel(const float* __restrict__ x) {
    constexpr int KP = 128;
    constexpr int S = 2 * KP + 8;    // 264
    extern __shared__ char smem[];
    const uint32_t Asm = smem_u32(smem);
    const uint32_t Bsm = Asm + 128 * S * 2;
    char* const Bc = smem + 128 * S * 2;
    const int tid = threadIdx.x;
    const int lane = tid & 31, wid = tid >> 5;
    const int wm = wid & 3, wn = wid >> 2;
    const int m0 = blockIdx.x * 128, n0 = blockIdx.y * 128;

    float acc[2][8][4] = {};
    for (int p = 0; p < 4; p++) {
        for (int task = tid; task < 128 * 16; task += 256) {
            const int r = task >> 4, o = task & 15;
            const float* src = x + (size_t)(m0 + r) * D_IN + p * KP + o * 8;
            const float4 v0 = *(const float4*)src;
            const float4 v1 = *(const float4*)(src + 4);
            __nv_bfloat16 h[8], l[8];
            const float vv[8] = {v0.x, v0.y, v0.z, v0.w, v1.x, v1.y, v1.z, v1.w};
#pragma unroll
            for (int i = 0; i < 8; i++) {
                h[i] = __float2bfloat16(vv[i]);
                l[i] = __float2bfloat16(vv[i] - __bfloat162float(h[i]));
            }
            *(uint4*)(smem + ((size_t)r * S + o * 8) * 2) = *(uint4*)h;
            *(uint4*)(smem + ((size_t)r * S + KP + o * 8) * 2) = *(uint4*)l;
        }
        for (int task = tid; task < 128 * 32; task += 256) {
            const int n = task >> 5, o = task & 31;
            const uint4 v = *(const uint4*)(g_WpD + (size_t)(n0 + n) * 1024 + p * 256 + o * 8);
            *(uint4*)(Bc + ((size_t)n * S + o * 8) * 2) = v;
        }
        __syncthreads();
        warp_gemm3<KP, S>(Asm, Bsm, wm, wn, lane, acc);
        __syncthreads();
    }

    const int g = lane >> 2;
#pragma unroll
    for (int ni = 0; ni < 8; ni++) {
        const int n = n0 + wn * 64 + ni * 8 + (lane & 3) * 2;
        const float sc0 = g_d1sc[n], sc1 = g_d1sc[n + 1];
        const float sh0 = g_d1sh[n], sh1 = g_d1sh[n + 1];
#pragma unroll
        for (int mi = 0; mi < 2; mi++) {
#pragma unroll
            for (int half = 0; half < 2; half++) {
                const int row = m0 + wm * 32 + mi * 16 + g + half * 8;
                float v0 = acc[mi][ni][half * 2 + 0] * sc0 + sh0;
                float v1 = acc[mi][ni][half * 2 + 1] * sc1 + sh1;
                v0 = (v0 >= 0.f) ? v0 : 0.2f * v0;
                v1 = (v1 >= 0.f) ? v1 : 0.2f * v1;
                __nv_bfloat16 h0 = __float2bfloat16(v0), h1 = __float2bfloat16(v1);
                __nv_bfloat162 hp; hp.x = h0; hp.y = h1;
                __nv_bfloat162 lp;
                lp.x = __float2bfloat16(v0 - __bfloat162float(h0));
                lp.y = __float2bfloat16(v1 - __bfloat162float(h1));
                *(__nv_bfloat162*)(g_acthi + (size_t)row * D_DENSE + n) = hp;
                *(__nv_bfloat162*)(g_actlo + (size_t)row * D_DENSE + n) = lp;
            }
        }
    }
}

// ---------------- Dense2 + softmax ----------------
__global__ __launch_bounds__(256) void dense2_softmax_kernel(
    const float* __restrict__ Wd2, const float* __restrict__ bd2, float* __restrict__ out) {
    __shared__ float Ws[H2 * NCLS];
    __shared__ float bs[NCLS];
    int tid = threadIdx.x;
    for (int i = tid; i < H2 * NCLS; i += blockDim.x) Ws[i] = Wd2[i];
    if (tid < NCLS) bs[tid] = bd2[tid];
    __syncthreads();
    int row = blockIdx.x * blockDim.x + tid;
    const __nv_bfloat16* hh = g_h2hi[0] + (size_t)row * H2;  // t=15 writes buffer 0
    const __nv_bfloat16* hl = g_h2lo[0] + (size_t)row * H2;
    float acc[NCLS];
#pragma unroll
    for (int j = 0; j < NCLS; j++) acc[j] = bs[j];
#pragma unroll
    for (int k = 0; k < H2; k++) {
        float xv = __bfloat162float(hh[k]) + __bfloat162float(hl[k]);
#pragma unroll
        for (int j = 0; j < NCLS; j++) acc[j] += xv * Ws[k * NCLS + j];
    }
    float m = acc[0];
#pragma unroll
    for (int j = 1; j < NCLS; j++) m = fmaxf(m, acc[j]);
    float ssum = 0.f;
#pragma unroll
    for (int j = 0; j < NCLS; j++) { acc[j] = expf(acc[j] - m); ssum += acc[j]; }
    float inv = 1.f / ssum;
#pragma unroll
    for (int j = 0; j < NCLS; j++) out[(size_t)row * NCLS + j] = acc[j] * inv;
}

// ---------------- launch ----------------
extern "C" void kernel_launch(void* const* d_in, const int* in_sizes, int n_in,
                              void* d_out, int out_size) {
    const float* x        = (const float*)d_in[0];
    const float* W_d1     = (const float*)d_in[1];
    const float* b_d1     = (const float*)d_in[2];
    const float* bn_gamma = (const float*)d_in[3];
    const float* bn_beta  = (const float*)d_in[4];
    const float* bn_mean  = (const float*)d_in[5];
    const float* bn_var   = (const float*)d_in[6];
    const float* Wx1      = (const float*)d_in[7];
    const float* Wh1      = (const float*)d_in[8];
    const float* b1       = (const float*)d_in[9];
    const float* Wx2      = (const float*)d_in[10];
    const float* Wh2      = (const float*)d_in[11];
    const float* b2       = (const float*)d_in[12];
    const float* W_d2     = (const float*)d_in[13];
    const float* b_d2     = (const float*)d_in[14];
    float* out = (float*)d_out;

    const int SM_STEP = 4 * 128 * (48 + 8) * 2;          // 57344 (covers BK=48 & BK=32)
    const int SMD     = 2 * 128 * (2 * 128 + 8) * 2;     // 135168

    cudaFuncSetAttribute(dense1_kernel, cudaFuncAttributeMaxDynamicSharedMemorySize, SMD);
    cudaFuncSetAttribute(lstm1_first_kernel, cudaFuncAttributeMaxDynamicSharedMemorySize, SM_STEP);
    cudaFuncSetAttribute(step_kernel, cudaFuncAttributeMaxDynamicSharedMemorySize, SM_STEP);

    prepack_kernel<<<256, 256>>>(Wx1, Wh1, b1, Wx2, Wh2, b2, W_d1, b_d1,
                                 bn_gamma, bn_beta, bn_mean, bn_var);
    init_state_kernel<<<2048, 256>>>();
    dense1_kernel<<<dim3(BATCH / 128, D_DENSE / 128), 256, SMD>>>(x);
    lstm1_first_kernel<<<1024, 512, SM_STEP>>>();
    for (int t = 0; t < TSTEPS; t++) {
        step_kernel<<<1280, 512, SM_STEP>>>(t, (t < TSTEPS - 1) ? 1 : 0);
    }
    dense2_softmax_kernel<<<BATCH / 256, 256>>>(W_d2, b_d2, out);
}

// round 6
// speedup vs baseline: 1.7199x; 1.0357x over previous
#include <cuda_runtime.h>
#include <cuda_bf16.h>
#include <math.h>
#include <stdint.h>

#define BATCH   32768
#define D_IN    512
#define D_DENSE 256
#define TSTEPS  16
#define FEAT    16
#define H1      128
#define H2      32
#define NCLS    10

// ---------------- state: row-major, bf16 hi/lo pairs ----------------
__device__ __nv_bfloat16 g_acthi[BATCH * D_DENSE], g_actlo[BATCH * D_DENSE];
__device__ __nv_bfloat16 g_h1hi[2][BATCH * H1],    g_h1lo[2][BATCH * H1];
__device__ __nv_bfloat16 g_h2hi[2][BATCH * H2],    g_h2lo[2][BATCH * H2];
__device__ float g_c1[BATCH * H1], g_c2[BATCH * H2];

// prepacked weights: row n (gate-interleaved), cols [hi(K)|lo(K)] bf16
__device__ __nv_bfloat16 g_Wp1[(4 * H1) * 2 * (FEAT + H1)];  // [512][288]
__device__ __nv_bfloat16 g_Wp2[(4 * H2) * 2 * (H1 + H2)];    // [128][320]
__device__ __nv_bfloat16 g_WpD[D_DENSE * 2 * D_IN];          // [256][1024], panel-major
__device__ float g_bc1[4 * H1], g_bc2[4 * H2];
__device__ float g_d1sc[D_DENSE], g_d1sh[D_DENSE];

// ---------------- helpers ----------------
__device__ __forceinline__ uint32_t smem_u32(const void* p) {
    uint32_t a;
    asm("{ .reg .u64 t; cvta.to.shared.u64 t, %1; cvt.u32.u64 %0, t; }" : "=r"(a) : "l"(p));
    return a;
}
__device__ __forceinline__ float ftanh(float x) {
    float y;
    asm("tanh.approx.f32 %0, %1;" : "=f"(y) : "f"(x));
    return y;
}
__device__ __forceinline__ float fsigm(float x) { return 0.5f * ftanh(0.5f * x) + 0.5f; }

__device__ __forceinline__ void ldsm4(uint32_t* r, uint32_t addr) {
    asm volatile("ldmatrix.sync.aligned.m8n8.x4.shared.b16 {%0,%1,%2,%3}, [%4];"
                 : "=r"(r[0]), "=r"(r[1]), "=r"(r[2]), "=r"(r[3]) : "r"(addr));
}
__device__ __forceinline__ void mma16816(float* d, const uint32_t* a, uint32_t b0, uint32_t b1) {
    asm volatile(
        "mma.sync.aligned.m16n8k16.row.col.f32.bf16.bf16.f32 "
        "{%0,%1,%2,%3}, {%4,%5,%6,%7}, {%8,%9}, {%0,%1,%2,%3};"
        : "+f"(d[0]), "+f"(d[1]), "+f"(d[2]), "+f"(d[3])
        : "r"(a[0]), "r"(a[1]), "r"(a[2]), "r"(a[3]), "r"(b0), "r"(b1));
}
__device__ __forceinline__ void cp16(uint32_t dst, const void* src) {
    asm volatile("cp.async.cg.shared.global [%0], [%1], 16;" :: "r"(dst), "l"(src));
}
#define CP_COMMIT() asm volatile("cp.async.commit_group;" ::: "memory")
#define CP_WAIT(n)  asm volatile("cp.async.wait_group %0;" :: "n"(n) : "memory")

// ============ fused LSTM step body: 256 thr, 8 warps 4Mx2N, warp 32x64, 3-stage pipe ======
template <int KX, int HID, int BK>
__device__ __forceinline__ void lstm_body(int t, int m0, int n0, char* smemc) {
    constexpr int K = KX + HID;
    constexpr int SA = BK + 8;               // halfs per smem row (row bytes /16 odd)
    constexpr int STG = 128 * SA * 2;        // bytes per A (or B) tile
    constexpr int CPT = K / BK;              // chunks per term
    constexpr int NCH = 3 * CPT;             // virtual chunks
    constexpr int GA = BK / 8;               // 16B groups per row
    const int tid = threadIdx.x;
    const int lane = tid & 31, wid = tid >> 5;
    const int wm = wid & 3, wn = wid >> 2;   // 4 x 2
    const uint32_t sbase = smem_u32(smemc);
    const int p = t & 1;

    const __nv_bfloat16 *xhi, *xlo, *hhi, *hlo;
    __nv_bfloat16 *hdhi, *hdlo;
    float* cbuf;
    const __nv_bfloat16* W;
    const float* bias;
    int xstride, xoff;
    if (HID == H1) {
        xhi = g_acthi; xlo = g_actlo; xstride = D_DENSE; xoff = t * FEAT;
        hhi = g_h1hi[p]; hlo = g_h1lo[p];
        hdhi = g_h1hi[p ^ 1]; hdlo = g_h1lo[p ^ 1];
        cbuf = g_c1; W = g_Wp1; bias = g_bc1;
    } else {
        xhi = g_h1hi[p ^ 1]; xlo = g_h1lo[p ^ 1]; xstride = H1; xoff = 0;
        hhi = g_h2hi[p]; hlo = g_h2lo[p];
        hdhi = g_h2hi[p ^ 1]; hdlo = g_h2lo[p ^ 1];
        cbuf = g_c2; W = g_Wp2; bias = g_bc2;
    }

    auto load_chunk = [&](int c) {
        const int term = c / CPT;
        const int kbase = (c % CPT) * BK;
        const __nv_bfloat16* xa = (term == 1) ? xlo : xhi;
        const __nv_bfloat16* ha = (term == 1) ? hlo : hhi;
        const int bofs = (term == 2) ? K : 0;
        const uint32_t As = sbase + (uint32_t)(c % 3) * (2 * STG);
        const uint32_t Bs = As + STG;
#pragma unroll
        for (int task = tid; task < 128 * GA; task += 256) {
            const int r = task / GA, gg = task % GA;
            const int col = kbase + gg * 8;
            const __nv_bfloat16* src = (col < KX)
                ? xa + (size_t)(m0 + r) * xstride + xoff + col
                : ha + (size_t)(m0 + r) * HID + (col - KX);
            cp16(As + (uint32_t)(r * SA + gg * 8) * 2, src);
        }
#pragma unroll
        for (int task = tid; task < 128 * GA; task += 256) {
            const int n = task / GA, gg = task % GA;
            cp16(Bs + (uint32_t)(n * SA + gg * 8) * 2,
                 W + (size_t)(n0 + n) * (2 * K) + bofs + kbase + gg * 8);
        }
    };

    const uint32_t aoffw = (uint32_t)((wm * 32 + (lane & 15)) * SA + ((lane >> 4) << 3)) * 2;
    const uint32_t boffw = (uint32_t)((wn * 64 + ((lane >> 4) << 3) + (lane & 7)) * SA
                                      + (((lane >> 3) & 1) << 3)) * 2;
    float acc[2][8][4] = {};

    load_chunk(0); CP_COMMIT();
    load_chunk(1); CP_COMMIT();
#pragma unroll 1
    for (int c = 0; c < NCH; c++) {
        CP_WAIT(1);            // chunk c landed (c+1 may be in flight)
        __syncthreads();       // all threads past compute(c-1); stage (c+2)%3 free
        if (c + 2 < NCH) load_chunk(c + 2);
        CP_COMMIT();           // commit (possibly empty) keeps group accounting uniform
        const uint32_t As = sbase + (uint32_t)(c % 3) * (2 * STG);
        const uint32_t Bs = As + STG;
#pragma unroll
        for (int kk = 0; kk < BK / 16; kk++) {
            uint32_t a0[4], a1[4], b[4][4];
            ldsm4(a0, As + aoffw + kk * 32);
            ldsm4(a1, As + aoffw + 16 * SA * 2 + kk * 32);
#pragma unroll
            for (int nj = 0; nj < 4; nj++)
                ldsm4(b[nj], Bs + boffw + nj * 16 * SA * 2 + kk * 32);
#pragma unroll
            for (int mi = 0; mi < 2; mi++) {
                const uint32_t* A = mi ? a1 : a0;
#pragma unroll
                for (int nj = 0; nj < 4; nj++) {
                    mma16816(acc[mi][2 * nj], A, b[nj][0], b[nj][1]);
                    mma16816(acc[mi][2 * nj + 1], A, b[nj][2], b[nj][3]);
                }
            }
        }
    }

    // epilogue (R4-verified, warp tile 32x64): pair-swap gates, fuse cell update
    const int g = lane >> 2;
    const bool odd = lane & 1;
#pragma unroll
    for (int ni = 0; ni < 8; ni++) {
        const int u = ((n0 + wn * 64 + ni * 8) >> 2) + ((lane & 2) >> 1);
        const float4 bb = *(const float4*)(bias + 4 * u);
#pragma unroll
        for (int mi = 0; mi < 2; mi++) {
            const float d0 = acc[mi][ni][0], d1 = acc[mi][ni][1];
            const float d2 = acc[mi][ni][2], d3 = acc[mi][ni][3];
            const float s0 = __shfl_xor_sync(0xffffffffu, odd ? d0 : d2, 1);
            const float s1 = __shfl_xor_sync(0xffffffffu, odd ? d1 : d3, 1);
            const float zi = (odd ? s0 : d0) + bb.x;
            const float zf = (odd ? s1 : d1) + bb.y;
            const float zg = (odd ? d2 : s0) + bb.z;
            const float zo = (odd ? d3 : s1) + bb.w;
            const int row = m0 + wm * 32 + mi * 16 + g + (odd ? 8 : 0);
            const float ig = fsigm(zi);
            const float fg = fsigm(zf);
            const float gg = ftanh(zg);
            const float og = fsigm(zo);
            const size_t off = (size_t)row * HID + u;
            const float cn = fg * cbuf[off] + ig * gg;
            cbuf[off] = cn;
            const float hv = og * ftanh(cn);
            const __nv_bfloat16 hh = __float2bfloat16(hv);
            hdhi[off] = hh;
            hdlo[off] = __float2bfloat16(hv - __bfloat162float(hh));
        }
    }
}

__global__ __launch_bounds__(256, 2) void lstm1_first_kernel() {
    extern __shared__ char smem[];
    lstm_body<FEAT, H1, 48>(0, (blockIdx.x & 255) * 128, (blockIdx.x >> 8) * 128, smem);
}

// combined: lstm2(t) on blocks [0,256); lstm1(t+1) on blocks [256,1280)
__global__ __launch_bounds__(256, 2) void step_kernel(int t, int do_l1) {
    extern __shared__ char smem[];
    if (blockIdx.x < 256) {
        lstm_body<H1, H2, 32>(t, blockIdx.x * 128, 0, smem);
    } else if (do_l1) {
        const int bx = blockIdx.x - 256;
        lstm_body<FEAT, H1, 48>(t + 1, (bx & 255) * 128, (bx >> 8) * 128, smem);
    }
}

// ---------------- init & prepack ----------------
__global__ void init_state_kernel() {
    int idx = blockIdx.x * blockDim.x + threadIdx.x;
    int stride = gridDim.x * blockDim.x;
    const __nv_bfloat16 z = __float2bfloat16(0.f);
    for (int i = idx; i < BATCH * H1; i += stride) {
        g_h1hi[0][i] = z; g_h1lo[0][i] = z; g_c1[i] = 0.f;
    }
    for (int i = idx; i < BATCH * H2; i += stride) {
        g_h2hi[0][i] = z; g_h2lo[0][i] = z; g_c2[i] = 0.f;
    }
}

__global__ void prepack_kernel(const float* __restrict__ Wx1, const float* __restrict__ Wh1,
                               const float* __restrict__ b1,
                               const float* __restrict__ Wx2, const float* __restrict__ Wh2,
                               const float* __restrict__ b2,
                               const float* __restrict__ W_d1, const float* __restrict__ b_d1,
                               const float* __restrict__ gamma, const float* __restrict__ beta,
                               const float* __restrict__ mean, const float* __restrict__ var) {
    int idx = blockIdx.x * blockDim.x + threadIdx.x;
    int stride = gridDim.x * blockDim.x;
    {
        constexpr int K = FEAT + H1;
        for (int i = idx; i < 4 * H1 * K; i += stride) {
            int n = i / K, k = i % K;
            int u = n >> 2, g = n & 3, src = g * H1 + u;
            float w = (k < FEAT) ? Wx1[k * 4 * H1 + src] : Wh1[(k - FEAT) * 4 * H1 + src];
            __nv_bfloat16 hi = __float2bfloat16(w);
            g_Wp1[(size_t)n * 2 * K + k] = hi;
            g_Wp1[(size_t)n * 2 * K + K + k] = __float2bfloat16(w - __bfloat162float(hi));
        }
        for (int i = idx; i < 4 * H1; i += stride) {
            int u = i >> 2, g = i & 3;
            g_bc1[i] = b1[g * H1 + u];
        }
    }
    {
        constexpr int K = H1 + H2;
        for (int i = idx; i < 4 * H2 * K; i += stride) {
            int n = i / K, k = i % K;
            int u = n >> 2, g = n & 3, src = g * H2 + u;
            float w = (k < H1) ? Wx2[k * 4 * H2 + src] : Wh2[(k - H1) * 4 * H2 + src];
            __nv_bfloat16 hi = __float2bfloat16(w);
            g_Wp2[(size_t)n * 2 * K + k] = hi;
            g_Wp2[(size_t)n * 2 * K + K + k] = __float2bfloat16(w - __bfloat162float(hi));
        }
        for (int i = idx; i < 4 * H2; i += stride) {
            int u = i >> 2, g = i & 3;
            g_bc2[i] = b2[g * H2 + u];
        }
    }
    // Dense1 weights: panel-major [n][p*256 + {hi 0..127 | lo 128..255}], p = k>>7
    for (int i = idx; i < D_DENSE * D_IN; i += stride) {
        int n = i / D_IN, k = i % D_IN;
        int p = k >> 7, kk = k & 127;
        float w = W_d1[(size_t)k * D_DENSE + n];
        __nv_bfloat16 hi = __float2bfloat16(w);
        g_WpD[(size_t)n * 1024 + p * 256 + kk] = hi;
        g_WpD[(size_t)n * 1024 + p * 256 + 128 + kk] = __float2bfloat16(w - __bfloat162float(hi));
    }
    for (int i = idx; i < D_DENSE; i += stride) {
        float sc = gamma[i] * rsqrtf(var[i] + 1e-3f);
        g_d1sc[i] = sc;
        g_d1sh[i] = beta[i] + (b_d1[i] - mean[i]) * sc;
    }
}

// ---------------- Dense1 (R4, verified): 256 threads, 8 warps 4x2, warp 32x64 ----------------
template <int K, int S>
__device__ __forceinline__ void warp_gemm3(uint32_t Asm, uint32_t Bsm,
                                           int wm, int wn, int lane, float acc[2][8][4]) {
    const uint32_t abase = Asm + ((((uint32_t)(wm * 32 + (lane & 15))) * S + ((lane >> 4) << 3)) << 1);
    const uint32_t bbase = Bsm + ((((uint32_t)(wn * 64 + ((lane >> 4) << 3) + (lane & 7))) * S
                                   + (((lane >> 3) & 1) << 3)) << 1);
#pragma unroll
    for (int term = 0; term < 3; term++) {
        const int ao = (term == 1) ? K : 0;
        const int bo = (term == 2) ? K : 0;
#pragma unroll
        for (int c = 0; c < K / 16; c++) {
            uint32_t a0[4], a1[4], b[4][4];
            ldsm4(a0, abase + ((ao + c * 16) << 1));
            ldsm4(a1, abase + ((16 * S + ao + c * 16) << 1));
#pragma unroll
            for (int nj = 0; nj < 4; nj++)
                ldsm4(b[nj], bbase + (((nj * 16) * S + bo + c * 16) << 1));
#pragma unroll
            for (int mi = 0; mi < 2; mi++) {
                const uint32_t* A = mi ? a1 : a0;
#pragma unroll
                for (int nj = 0; nj < 4; nj++) {
                    mma16816(acc[mi][2 * nj], A, b[nj][0], b[nj][1]);
                    mma16816(acc[mi][2 * nj + 1], A, b[nj][2], b[nj][3]);
                }
            }
        }
    }
}

__global__ __launch_bounds__(256, 1) void dense1_kernel(const float* __restrict__ x) {
    constexpr int KP = 128;
    constexpr int S = 2 * KP + 8;    // 264
    extern __shared__ char smem[];
    const uint32_t Asm = smem_u32(smem);
    const uint32_t Bsm = Asm + 128 * S * 2;
    char* const Bc = smem + 128 * S * 2;
    const int tid = threadIdx.x;
    const int lane = tid & 31, wid = tid >> 5;
    const int wm = wid & 3, wn = wid >> 2;
    const int m0 = blockIdx.x * 128, n0 = blockIdx.y * 128;

    float acc[2][8][4] = {};
    for (int p = 0; p < 4; p++) {
        for (int task = tid; task < 128 * 16; task += 256) {
            const int r = task >> 4, o = task & 15;
            const float* src = x + (size_t)(m0 + r) * D_IN + p * KP + o * 8;
            const float4 v0 = *(const float4*)src;
            const float4 v1 = *(const float4*)(src + 4);
            __nv_bfloat16 h[8], l[8];
            const float vv[8] = {v0.x, v0.y, v0.z, v0.w, v1.x, v1.y, v1.z, v1.w};
#pragma unroll
            for (int i = 0; i < 8; i++) {
                h[i] = __float2bfloat16(vv[i]);
                l[i] = __float2bfloat16(vv[i] - __bfloat162float(h[i]));
            }
            *(uint4*)(smem + ((size_t)r * S + o * 8) * 2) = *(uint4*)h;
            *(uint4*)(smem + ((size_t)r * S + KP + o * 8) * 2) = *(uint4*)l;
        }
        for (int task = tid; task < 128 * 32; task += 256) {
            const int n = task >> 5, o = task & 31;
            const uint4 v = *(const uint4*)(g_WpD + (size_t)(n0 + n) * 1024 + p * 256 + o * 8);
            *(uint4*)(Bc + ((size_t)n * S + o * 8) * 2) = v;
        }
        __syncthreads();
        warp_gemm3<KP, S>(Asm, Bsm, wm, wn, lane, acc);
        __syncthreads();
    }

    const int g = lane >> 2;
#pragma unroll
    for (int ni = 0; ni < 8; ni++) {
        const int n = n0 + wn * 64 + ni * 8 + (lane & 3) * 2;
        const float sc0 = g_d1sc[n], sc1 = g_d1sc[n + 1];
        const float sh0 = g_d1sh[n], sh1 = g_d1sh[n + 1];
#pragma unroll
        for (int mi = 0; mi < 2; mi++) {
#pragma unroll
            for (int half = 0; half < 2; half++) {
                const int row = m0 + wm * 32 + mi * 16 + g + half * 8;
                float v0 = acc[mi][ni][half * 2 + 0] * sc0 + sh0;
                float v1 = acc[mi][ni][half * 2 + 1] * sc1 + sh1;
                v0 = (v0 >= 0.f) ? v0 : 0.2f * v0;
                v1 = (v1 >= 0.f) ? v1 : 0.2f * v1;
                __nv_bfloat16 h0 = __float2bfloat16(v0), h1 = __float2bfloat16(v1);
                __nv_bfloat162 hp; hp.x = h0; hp.y = h1;
                __nv_bfloat162 lp;
                lp.x = __float2bfloat16(v0 - __bfloat162float(h0));
                lp.y = __float2bfloat16(v1 - __bfloat162float(h1));
                *(__nv_bfloat162*)(g_acthi + (size_t)row * D_DENSE + n) = hp;
                *(__nv_bfloat162*)(g_actlo + (size_t)row * D_DENSE + n) = lp;
            }
        }
    }
}

// ---------------- Dense2 + softmax ----------------
__global__ __launch_bounds__(256) void dense2_softmax_kernel(
    const float* __restrict__ Wd2, const float* __restrict__ bd2, float* __restrict__ out) {
    __shared__ float Ws[H2 * NCLS];
    __shared__ float bs[NCLS];
    int tid = threadIdx.x;
    for (int i = tid; i < H2 * NCLS; i += blockDim.x) Ws[i] = Wd2[i];
    if (tid < NCLS) bs[tid] = bd2[tid];
    __syncthreads();
    int row = blockIdx.x * blockDim.x + tid;
    const __nv_bfloat16* hh = g_h2hi[0] + (size_t)row * H2;  // t=15 writes buffer 0
    const __nv_bfloat16* hl = g_h2lo[0] + (size_t)row * H2;
    float acc[NCLS];
#pragma unroll
    for (int j = 0; j < NCLS; j++) acc[j] = bs[j];
#pragma unroll
    for (int k = 0; k < H2; k++) {
        float xv = __bfloat162float(hh[k]) + __bfloat162float(hl[k]);
#pragma unroll
        for (int j = 0; j < NCLS; j++) acc[j] += xv * Ws[k * NCLS + j];
    }
    float m = acc[0];
#pragma unroll
    for (int j = 1; j < NCLS; j++) m = fmaxf(m, acc[j]);
    float ssum = 0.f;
#pragma unroll
    for (int j = 0; j < NCLS; j++) { acc[j] = expf(acc[j] - m); ssum += acc[j]; }
    float inv = 1.f / ssum;
#pragma unroll
    for (int j = 0; j < NCLS; j++) out[(size_t)row * NCLS + j] = acc[j] * inv;
}

// ---------------- launch ----------------
extern "C" void kernel_launch(void* const* d_in, const int* in_sizes, int n_in,
                              void* d_out, int out_size) {
    const float* x        = (const float*)d_in[0];
    const float* W_d1     = (const float*)d_in[1];
    const float* b_d1     = (const float*)d_in[2];
    const float* bn_gamma = (const float*)d_in[3];
    const float* bn_beta  = (const float*)d_in[4];
    const float* bn_mean  = (const float*)d_in[5];
    const float* bn_var   = (const float*)d_in[6];
    const float* Wx1      = (const float*)d_in[7];
    const float* Wh1      = (const float*)d_in[8];
    const float* b1       = (const float*)d_in[9];
    const float* Wx2      = (const float*)d_in[10];
    const float* Wh2      = (const float*)d_in[11];
    const float* b2       = (const float*)d_in[12];
    const float* W_d2     = (const float*)d_in[13];
    const float* b_d2     = (const float*)d_in[14];
    float* out = (float*)d_out;

    const int SM_STEP = 3 * 2 * 128 * (48 + 8) * 2;      // 86016 (3-stage, covers BK=48 & BK=32)
    const int SMD     = 2 * 128 * (2 * 128 + 8) * 2;     // 135168

    cudaFuncSetAttribute(dense1_kernel, cudaFuncAttributeMaxDynamicSharedMemorySize, SMD);
    cudaFuncSetAttribute(lstm1_first_kernel, cudaFuncAttributeMaxDynamicSharedMemorySize, SM_STEP);
    cudaFuncSetAttribute(step_kernel, cudaFuncAttributeMaxDynamicSharedMemorySize, SM_STEP);

    prepack_kernel<<<256, 256>>>(Wx1, Wh1, b1, Wx2, Wh2, b2, W_d1, b_d1,
                                 bn_gamma, bn_beta, bn_mean, bn_var);
    init_state_kernel<<<2048, 256>>>();
    dense1_kernel<<<dim3(BATCH / 128, D_DENSE / 128), 256, SMD>>>(x);
    lstm1_first_kernel<<<1024, 256, SM_STEP>>>();
    for (int t = 0; t < TSTEPS; t++) {
        step_kernel<<<1280, 256, SM_STEP>>>(t, (t < TSTEPS - 1) ? 1 : 0);
    }
    dense2_softmax_kernel<<<BATCH / 256, 256>>>(W_d2, b_d2, out);
}

// round 7
// speedup vs baseline: 1.8136x; 1.0545x over previous
#include <cuda_runtime.h>
#include <cuda_bf16.h>
#include <math.h>
#include <stdint.h>

#define BATCH   32768
#define D_IN    512
#define D_DENSE 256
#define TSTEPS  16
#define FEAT    16
#define H1      128
#define H2      32
#define NCLS    10

// ---------------- state: row-major, bf16 hi/lo pairs ----------------
__device__ __nv_bfloat16 g_acthi[BATCH * D_DENSE], g_actlo[BATCH * D_DENSE];
__device__ __nv_bfloat16 g_h1hi[2][BATCH * H1],    g_h1lo[2][BATCH * H1];
__device__ __nv_bfloat16 g_h2hi[2][BATCH * H2],    g_h2lo[2][BATCH * H2];
__device__ float g_c1[BATCH * H1], g_c2[BATCH * H2];

// prepacked weights: row n (gate-interleaved), cols [hi(K)|lo(K)] bf16
__device__ __nv_bfloat16 g_Wp1[(4 * H1) * 2 * (FEAT + H1)];  // [512][288]
__device__ __nv_bfloat16 g_Wp2[(4 * H2) * 2 * (H1 + H2)];    // [128][320]
__device__ __nv_bfloat16 g_WpD[D_DENSE * 2 * D_IN];          // [256][1024], panel-major
__device__ float g_bc1[4 * H1], g_bc2[4 * H2];
__device__ float g_d1sc[D_DENSE], g_d1sh[D_DENSE];

// ---------------- helpers ----------------
__device__ __forceinline__ uint32_t smem_u32(const void* p) {
    uint32_t a;
    asm("{ .reg .u64 t; cvta.to.shared.u64 t, %1; cvt.u32.u64 %0, t; }" : "=r"(a) : "l"(p));
    return a;
}
__device__ __forceinline__ float ftanh(float x) {
    float y;
    asm("tanh.approx.f32 %0, %1;" : "=f"(y) : "f"(x));
    return y;
}
__device__ __forceinline__ float fsigm(float x) { return 0.5f * ftanh(0.5f * x) + 0.5f; }

__device__ __forceinline__ void ldsm4(uint32_t* r, uint32_t addr) {
    asm volatile("ldmatrix.sync.aligned.m8n8.x4.shared.b16 {%0,%1,%2,%3}, [%4];"
                 : "=r"(r[0]), "=r"(r[1]), "=r"(r[2]), "=r"(r[3]) : "r"(addr));
}
__device__ __forceinline__ void mma16816(float* d, const uint32_t* a, uint32_t b0, uint32_t b1) {
    asm volatile(
        "mma.sync.aligned.m16n8k16.row.col.f32.bf16.bf16.f32 "
        "{%0,%1,%2,%3}, {%4,%5,%6,%7}, {%8,%9}, {%0,%1,%2,%3};"
        : "+f"(d[0]), "+f"(d[1]), "+f"(d[2]), "+f"(d[3])
        : "r"(a[0]), "r"(a[1]), "r"(a[2]), "r"(a[3]), "r"(b0), "r"(b1));
}
__device__ __forceinline__ void cp16(uint32_t dst, const void* src) {
    asm volatile("cp.async.cg.shared.global [%0], [%1], 16;" :: "r"(dst), "l"(src));
}
#define CP_COMMIT() asm volatile("cp.async.commit_group;" ::: "memory")
#define CP_WAIT(n)  asm volatile("cp.async.wait_group %0;" :: "n"(n) : "memory")

// ======= fused LSTM step body: B weights fully smem-resident, A streamed 2-stage =========
// 256 threads, 8 warps 4(M)x2(N), warp tile 32x64, CTA tile 128x128.
template <int KX, int HID, int BK>
__device__ __forceinline__ void lstm_body(int t, int m0, int n0, char* smemc) {
    constexpr int K = KX + HID;
    constexpr int SA = BK + 8;               // A row length in halfs (row bytes /16 odd)
    constexpr int STG_A = 128 * SA * 2;
    constexpr int SB = 2 * K + 8;            // B row length in halfs
    constexpr int CPT = K / BK;              // chunks per (hi|lo) pass
    constexpr int NCH = 2 * CPT;             // hi chunks then lo chunks
    constexpr int GA = BK / 8;
    constexpr int GB = 2 * K / 8;
    const int tid = threadIdx.x;
    const int lane = tid & 31, wid = tid >> 5;
    const int wm = wid & 3, wn = wid >> 2;   // 4 x 2
    const uint32_t sbase = smem_u32(smemc);
    const uint32_t Bbase = sbase + 2 * STG_A;
    const int p = t & 1;

    const __nv_bfloat16 *xhi, *xlo, *hhi, *hlo;
    __nv_bfloat16 *hdhi, *hdlo;
    float* cbuf;
    const __nv_bfloat16* W;
    const float* bias;
    int xstride, xoff;
    if (HID == H1) {
        xhi = g_acthi; xlo = g_actlo; xstride = D_DENSE; xoff = t * FEAT;
        hhi = g_h1hi[p]; hlo = g_h1lo[p];
        hdhi = g_h1hi[p ^ 1]; hdlo = g_h1lo[p ^ 1];
        cbuf = g_c1; W = g_Wp1; bias = g_bc1;
    } else {
        xhi = g_h1hi[p ^ 1]; xlo = g_h1lo[p ^ 1]; xstride = H1; xoff = 0;
        hhi = g_h2hi[p]; hlo = g_h2lo[p];
        hdhi = g_h2hi[p ^ 1]; hdlo = g_h2lo[p ^ 1];
        cbuf = g_c2; W = g_Wp2; bias = g_bc2;
    }

    auto load_a = [&](int c) {
        const bool hi = c < CPT;
        const int kbase = (hi ? c : c - CPT) * BK;
        const __nv_bfloat16* xa = hi ? xhi : xlo;
        const __nv_bfloat16* ha = hi ? hhi : hlo;
        const uint32_t As = sbase + (uint32_t)(c & 1) * STG_A;
#pragma unroll
        for (int task = tid; task < 128 * GA; task += 256) {
            const int r = task / GA, gg = task % GA;
            const int col = kbase + gg * 8;
            const __nv_bfloat16* src = (col < KX)
                ? xa + (size_t)(m0 + r) * xstride + xoff + col
                : ha + (size_t)(m0 + r) * HID + (col - KX);
            cp16(As + (uint32_t)(r * SA + gg * 8) * 2, src);
        }
    };

    // prologue: resident B + first A chunk, one group
#pragma unroll
    for (int task = tid; task < 128 * GB; task += 256) {
        const int n = task / GB, gg = task % GB;
        cp16(Bbase + (uint32_t)(n * SB + gg * 8) * 2,
             W + (size_t)(n0 + n) * (2 * K) + gg * 8);
    }
    load_a(0);
    CP_COMMIT();

    const uint32_t aoffw = (uint32_t)((wm * 32 + (lane & 15)) * SA + ((lane >> 4) << 3)) * 2;
    // B row/lane base (col added per use): row = wn*64 + (lane>>4)*8 + (lane&7), col8 = ((lane>>3)&1)*8
    const uint32_t brow = (uint32_t)(wn * 64 + ((lane >> 4) << 3) + (lane & 7));
    const uint32_t bcol8 = (uint32_t)(((lane >> 3) & 1) << 3);
    float acc[2][8][4] = {};

#pragma unroll 1
    for (int c = 0; c < NCH; c++) {
        CP_WAIT(0);            // A(c) (and B at c=0) landed for this thread
        __syncthreads();       // visible to all; compute(c-1) finished everywhere
        if (c + 1 < NCH) { load_a(c + 1); CP_COMMIT(); }  // overlaps compute(c)
        const bool hi = c < CPT;
        const int kbase = (hi ? c : c - CPT) * BK;
        const uint32_t As = sbase + (uint32_t)(c & 1) * STG_A;
#pragma unroll
        for (int kk = 0; kk < BK / 16; kk++) {
            uint32_t a0[4], a1[4];
            ldsm4(a0, As + aoffw + kk * 32);
            ldsm4(a1, As + aoffw + 16 * SA * 2 + kk * 32);
            const int nsets = hi ? 2 : 1;
#pragma unroll
            for (int set = 0; set < 2; set++) {
                if (set >= nsets) break;
                const uint32_t cofs = (uint32_t)(kbase + kk * 16 + (set ? K : 0)) + bcol8;
                uint32_t b[4][4];
#pragma unroll
                for (int nj = 0; nj < 4; nj++)
                    ldsm4(b[nj], Bbase + ((brow + nj * 16) * SB + cofs) * 2);
#pragma unroll
                for (int mi = 0; mi < 2; mi++) {
                    const uint32_t* A = mi ? a1 : a0;
#pragma unroll
                    for (int nj = 0; nj < 4; nj++) {
                        mma16816(acc[mi][2 * nj], A, b[nj][0], b[nj][1]);
                        mma16816(acc[mi][2 * nj + 1], A, b[nj][2], b[nj][3]);
                    }
                }
            }
        }
    }

    // epilogue (verified): pair-swap gates, fuse cell update
    const int g = lane >> 2;
    const bool odd = lane & 1;
#pragma unroll
    for (int ni = 0; ni < 8; ni++) {
        const int u = ((n0 + wn * 64 + ni * 8) >> 2) + ((lane & 2) >> 1);
        const float4 bb = *(const float4*)(bias + 4 * u);
#pragma unroll
        for (int mi = 0; mi < 2; mi++) {
            const float d0 = acc[mi][ni][0], d1 = acc[mi][ni][1];
            const float d2 = acc[mi][ni][2], d3 = acc[mi][ni][3];
            const float s0 = __shfl_xor_sync(0xffffffffu, odd ? d0 : d2, 1);
            const float s1 = __shfl_xor_sync(0xffffffffu, odd ? d1 : d3, 1);
            const float zi = (odd ? s0 : d0) + bb.x;
            const float zf = (odd ? s1 : d1) + bb.y;
            const float zg = (odd ? d2 : s0) + bb.z;
            const float zo = (odd ? d3 : s1) + bb.w;
            const int row = m0 + wm * 32 + mi * 16 + g + (odd ? 8 : 0);
            const float ig = fsigm(zi);
            const float fg = fsigm(zf);
            const float gg = ftanh(zg);
            const float og = fsigm(zo);
            const size_t off = (size_t)row * HID + u;
            const float cn = fg * cbuf[off] + ig * gg;
            cbuf[off] = cn;
            const float hv = og * ftanh(cn);
            const __nv_bfloat16 hh = __float2bfloat16(hv);
            hdhi[off] = hh;
            hdlo[off] = __float2bfloat16(hv - __bfloat162float(hh));
        }
    }
}

__global__ __launch_bounds__(256, 2) void lstm1_first_kernel() {
    extern __shared__ char smem[];
    lstm_body<FEAT, H1, 48>(0, (blockIdx.x & 255) * 128, (blockIdx.x >> 8) * 128, smem);
}

// combined: lstm2(t) on blocks [0,256); lstm1(t+1) on blocks [256,1280)
__global__ __launch_bounds__(256, 2) void step_kernel(int t, int do_l1) {
    extern __shared__ char smem[];
    if (blockIdx.x < 256) {
        lstm_body<H1, H2, 32>(t, blockIdx.x * 128, 0, smem);
    } else if (do_l1) {
        const int bx = blockIdx.x - 256;
        lstm_body<FEAT, H1, 48>(t + 1, (bx & 255) * 128, (bx >> 8) * 128, smem);
    }
}

// ---------------- init & prepack ----------------
__global__ void init_state_kernel() {
    int idx = blockIdx.x * blockDim.x + threadIdx.x;
    int stride = gridDim.x * blockDim.x;
    const __nv_bfloat16 z = __float2bfloat16(0.f);
    for (int i = idx; i < BATCH * H1; i += stride) {
        g_h1hi[0][i] = z; g_h1lo[0][i] = z; g_c1[i] = 0.f;
    }
    for (int i = idx; i < BATCH * H2; i += stride) {
        g_h2hi[0][i] = z; g_h2lo[0][i] = z; g_c2[i] = 0.f;
    }
}

__global__ void prepack_kernel(const float* __restrict__ Wx1, const float* __restrict__ Wh1,
                               const float* __restrict__ b1,
                               const float* __restrict__ Wx2, const float* __restrict__ Wh2,
                               const float* __restrict__ b2,
                               const float* __restrict__ W_d1, const float* __restrict__ b_d1,
                               const float* __restrict__ gamma, const float* __restrict__ beta,
                               const float* __restrict__ mean, const float* __restrict__ var) {
    int idx = blockIdx.x * blockDim.x + threadIdx.x;
    int stride = gridDim.x * blockDim.x;
    {
        constexpr int K = FEAT + H1;
        for (int i = idx; i < 4 * H1 * K; i += stride) {
            int n = i / K, k = i % K;
            int u = n >> 2, g = n & 3, src = g * H1 + u;
            float w = (k < FEAT) ? Wx1[k * 4 * H1 + src] : Wh1[(k - FEAT) * 4 * H1 + src];
            __nv_bfloat16 hi = __float2bfloat16(w);
            g_Wp1[(size_t)n * 2 * K + k] = hi;
            g_Wp1[(size_t)n * 2 * K + K + k] = __float2bfloat16(w - __bfloat162float(hi));
        }
        for (int i = idx; i < 4 * H1; i += stride) {
            int u = i >> 2, g = i & 3;
            g_bc1[i] = b1[g * H1 + u];
        }
    }
    {
        constexpr int K = H1 + H2;
        for (int i = idx; i < 4 * H2 * K; i += stride) {
            int n = i / K, k = i % K;
            int u = n >> 2, g = n & 3, src = g * H2 + u;
            float w = (k < H1) ? Wx2[k * 4 * H2 + src] : Wh2[(k - H1) * 4 * H2 + src];
            __nv_bfloat16 hi = __float2bfloat16(w);
            g_Wp2[(size_t)n * 2 * K + k] = hi;
            g_Wp2[(size_t)n * 2 * K + K + k] = __float2bfloat16(w - __bfloat162float(hi));
        }
        for (int i = idx; i < 4 * H2; i += stride) {
            int u = i >> 2, g = i & 3;
            g_bc2[i] = b2[g * H2 + u];
        }
    }
    // Dense1 weights: panel-major [n][p*256 + {hi 0..127 | lo 128..255}], p = k>>7
    for (int i = idx; i < D_DENSE * D_IN; i += stride) {
        int n = i / D_IN, k = i % D_IN;
        int p = k >> 7, kk = k & 127;
        float w = W_d1[(size_t)k * D_DENSE + n];
        __nv_bfloat16 hi = __float2bfloat16(w);
        g_WpD[(size_t)n * 1024 + p * 256 + kk] = hi;
        g_WpD[(size_t)n * 1024 + p * 256 + 128 + kk] = __float2bfloat16(w - __bfloat162float(hi));
    }
    for (int i = idx; i < D_DENSE; i += stride) {
        float sc = gamma[i] * rsqrtf(var[i] + 1e-3f);
        g_d1sc[i] = sc;
        g_d1sh[i] = beta[i] + (b_d1[i] - mean[i]) * sc;
    }
}

// ---------------- Dense1 (verified): 256 threads, 8 warps 4x2, warp 32x64 ----------------
template <int K, int S>
__device__ __forceinline__ void warp_gemm3(uint32_t Asm, uint32_t Bsm,
                                           int wm, int wn, int lane, float acc[2][8][4]) {
    const uint32_t abase = Asm + ((((uint32_t)(wm * 32 + (lane & 15))) * S + ((lane >> 4) << 3)) << 1);
    const uint32_t bbase = Bsm + ((((uint32_t)(wn * 64 + ((lane >> 4) << 3) + (lane & 7))) * S
                                   + (((lane >> 3) & 1) << 3)) << 1);
#pragma unroll
    for (int term = 0; term < 3; term++) {
        const int ao = (term == 1) ? K : 0;
        const int bo = (term == 2) ? K : 0;
#pragma unroll
        for (int c = 0; c < K / 16; c++) {
            uint32_t a0[4], a1[4], b[4][4];
            ldsm4(a0, abase + ((ao + c * 16) << 1));
            ldsm4(a1, abase + ((16 * S + ao + c * 16) << 1));
#pragma unroll
            for (int nj = 0; nj < 4; nj++)
                ldsm4(b[nj], bbase + (((nj * 16) * S + bo + c * 16) << 1));
#pragma unroll
            for (int mi = 0; mi < 2; mi++) {
                const uint32_t* A = mi ? a1 : a0;
#pragma unroll
                for (int nj = 0; nj < 4; nj++) {
                    mma16816(acc[mi][2 * nj], A, b[nj][0], b[nj][1]);
                    mma16816(acc[mi][2 * nj + 1], A, b[nj][2], b[nj][3]);
                }
            }
        }
    }
}

__global__ __launch_bounds__(256, 1) void dense1_kernel(const float* __restrict__ x) {
    constexpr int KP = 128;
    constexpr int S = 2 * KP + 8;    // 264
    extern __shared__ char smem[];
    const uint32_t Asm = smem_u32(smem);
    const uint32_t Bsm = Asm + 128 * S * 2;
    char* const Bc = smem + 128 * S * 2;
    const int tid = threadIdx.x;
    const int lane = tid & 31, wid = tid >> 5;
    const int wm = wid & 3, wn = wid >> 2;
    const int m0 = blockIdx.x * 128, n0 = blockIdx.y * 128;

    float acc[2][8][4] = {};
    for (int p = 0; p < 4; p++) {
        for (int task = tid; task < 128 * 16; task += 256) {
            const int r = task >> 4, o = task & 15;
            const float* src = x + (size_t)(m0 + r) * D_IN + p * KP + o * 8;
            const float4 v0 = *(const float4*)src;
            const float4 v1 = *(const float4*)(src + 4);
            __nv_bfloat16 h[8], l[8];
            const float vv[8] = {v0.x, v0.y, v0.z, v0.w, v1.x, v1.y, v1.z, v1.w};
#pragma unroll
            for (int i = 0; i < 8; i++) {
                h[i] = __float2bfloat16(vv[i]);
                l[i] = __float2bfloat16(vv[i] - __bfloat162float(h[i]));
            }
            *(uint4*)(smem + ((size_t)r * S + o * 8) * 2) = *(uint4*)h;
            *(uint4*)(smem + ((size_t)r * S + KP + o * 8) * 2) = *(uint4*)l;
        }
        for (int task = tid; task < 128 * 32; task += 256) {
            const int n = task >> 5, o = task & 31;
            const uint4 v = *(const uint4*)(g_WpD + (size_t)(n0 + n) * 1024 + p * 256 + o * 8);
            *(uint4*)(Bc + ((size_t)n * S + o * 8) * 2) = v;
        }
        __syncthreads();
        warp_gemm3<KP, S>(Asm, Bsm, wm, wn, lane, acc);
        __syncthreads();
    }

    const int g = lane >> 2;
#pragma unroll
    for (int ni = 0; ni < 8; ni++) {
        const int n = n0 + wn * 64 + ni * 8 + (lane & 3) * 2;
        const float sc0 = g_d1sc[n], sc1 = g_d1sc[n + 1];
        const float sh0 = g_d1sh[n], sh1 = g_d1sh[n + 1];
#pragma unroll
        for (int mi = 0; mi < 2; mi++) {
#pragma unroll
            for (int half = 0; half < 2; half++) {
                const int row = m0 + wm * 32 + mi * 16 + g + half * 8;
                float v0 = acc[mi][ni][half * 2 + 0] * sc0 + sh0;
                float v1 = acc[mi][ni][half * 2 + 1] * sc1 + sh1;
                v0 = (v0 >= 0.f) ? v0 : 0.2f * v0;
                v1 = (v1 >= 0.f) ? v1 : 0.2f * v1;
                __nv_bfloat16 h0 = __float2bfloat16(v0), h1 = __float2bfloat16(v1);
                __nv_bfloat162 hp; hp.x = h0; hp.y = h1;
                __nv_bfloat162 lp;
                lp.x = __float2bfloat16(v0 - __bfloat162float(h0));
                lp.y = __float2bfloat16(v1 - __bfloat162float(h1));
                *(__nv_bfloat162*)(g_acthi + (size_t)row * D_DENSE + n) = hp;
                *(__nv_bfloat162*)(g_actlo + (size_t)row * D_DENSE + n) = lp;
            }
        }
    }
}

// ---------------- Dense2 + softmax ----------------
__global__ __launch_bounds__(256) void dense2_softmax_kernel(
    const float* __restrict__ Wd2, const float* __restrict__ bd2, float* __restrict__ out) {
    __shared__ float Ws[H2 * NCLS];
    __shared__ float bs[NCLS];
    int tid = threadIdx.x;
    for (int i = tid; i < H2 * NCLS; i += blockDim.x) Ws[i] = Wd2[i];
    if (tid < NCLS) bs[tid] = bd2[tid];
    __syncthreads();
    int row = blockIdx.x * blockDim.x + tid;
    const __nv_bfloat16* hh = g_h2hi[0] + (size_t)row * H2;  // t=15 writes buffer 0
    const __nv_bfloat16* hl = g_h2lo[0] + (size_t)row * H2;
    float acc[NCLS];
#pragma unroll
    for (int j = 0; j < NCLS; j++) acc[j] = bs[j];
#pragma unroll
    for (int k = 0; k < H2; k++) {
        float xv = __bfloat162float(hh[k]) + __bfloat162float(hl[k]);
#pragma unroll
        for (int j = 0; j < NCLS; j++) acc[j] += xv * Ws[k * NCLS + j];
    }
    float m = acc[0];
#pragma unroll
    for (int j = 1; j < NCLS; j++) m = fmaxf(m, acc[j]);
    float ssum = 0.f;
#pragma unroll
    for (int j = 0; j < NCLS; j++) { acc[j] = expf(acc[j] - m); ssum += acc[j]; }
    float inv = 1.f / ssum;
#pragma unroll
    for (int j = 0; j < NCLS; j++) out[(size_t)row * NCLS + j] = acc[j] * inv;
}

// ---------------- launch ----------------
extern "C" void kernel_launch(void* const* d_in, const int* in_sizes, int n_in,
                              void* d_out, int out_size) {
    const float* x        = (const float*)d_in[0];
    const float* W_d1     = (const float*)d_in[1];
    const float* b_d1     = (const float*)d_in[2];
    const float* bn_gamma = (const float*)d_in[3];
    const float* bn_beta  = (const float*)d_in[4];
    const float* bn_mean  = (const float*)d_in[5];
    const float* bn_var   = (const float*)d_in[6];
    const float* Wx1      = (const float*)d_in[7];
    const float* Wh1      = (const float*)d_in[8];
    const float* b1       = (const float*)d_in[9];
    const float* Wx2      = (const float*)d_in[10];
    const float* Wh2      = (const float*)d_in[11];
    const float* b2       = (const float*)d_in[12];
    const float* W_d2     = (const float*)d_in[13];
    const float* b_d2     = (const float*)d_in[14];
    float* out = (float*)d_out;

    // LSTM1: 2*128*56*2 + 128*296*2 = 28672 + 75776 = 104448
    // LSTM2: 2*128*40*2 + 128*328*2 = 20480 + 83968 = 104448
    const int SM_STEP = 104448;
    const int SMD     = 2 * 128 * (2 * 128 + 8) * 2;     // 135168

    cudaFuncSetAttribute(dense1_kernel, cudaFuncAttributeMaxDynamicSharedMemorySize, SMD);
    cudaFuncSetAttribute(lstm1_first_kernel, cudaFuncAttributeMaxDynamicSharedMemorySize, SM_STEP);
    cudaFuncSetAttribute(step_kernel, cudaFuncAttributeMaxDynamicSharedMemorySize, SM_STEP);

    prepack_kernel<<<256, 256>>>(Wx1, Wh1, b1, Wx2, Wh2, b2, W_d1, b_d1,
                                 bn_gamma, bn_beta, bn_mean, bn_var);
    init_state_kernel<<<2048, 256>>>();
    dense1_kernel<<<dim3(BATCH / 128, D_DENSE / 128), 256, SMD>>>(x);
    lstm1_first_kernel<<<1024, 256, SM_STEP>>>();
    for (int t = 0; t < TSTEPS; t++) {
        step_kernel<<<1280, 256, SM_STEP>>>(t, (t < TSTEPS - 1) ? 1 : 0);
    }
    dense2_softmax_kernel<<<BATCH / 256, 256>>>(W_d2, b_d2, out);
}

// round 8
// speedup vs baseline: 2.8221x; 1.5561x over previous
#include <cuda_runtime.h>
#include <cuda_bf16.h>
#include <math.h>
#include <stdint.h>

#define BATCH   32768
#define D_IN    512
#define D_DENSE 256
#define TSTEPS  16
#define FEAT    16
#define H1      128
#define H2      32
#define NCLS    10

// ---------------- state: COLUMN-major [feature][BATCH], bf16 hi/lo pairs ----------------
__device__ __nv_bfloat16 g_acthi[D_DENSE * BATCH], g_actlo[D_DENSE * BATCH];
__device__ __nv_bfloat16 g_h1hi[2][H1 * BATCH],    g_h1lo[2][H1 * BATCH];
__device__ __nv_bfloat16 g_h2hi[2][H2 * BATCH],    g_h2lo[2][H2 * BATCH];
__device__ float g_c1[H1 * BATCH], g_c2[H2 * BATCH];

// prepacked weights: row n (gate-interleaved), cols [hi(K)|lo(K)] bf16
__device__ __nv_bfloat16 g_Wp1[(4 * H1) * 2 * (FEAT + H1)];  // [512][288]
__device__ __nv_bfloat16 g_Wp2[(4 * H2) * 2 * (H1 + H2)];    // [128][320]
__device__ __nv_bfloat16 g_WpD[D_DENSE * 2 * D_IN];          // [256][1024], panel-major
__device__ float g_bc1[4 * H1], g_bc2[4 * H2];
__device__ float g_d1sc[D_DENSE], g_d1sh[D_DENSE];

// ---------------- helpers ----------------
__device__ __forceinline__ uint32_t smem_u32(const void* p) {
    uint32_t a;
    asm("{ .reg .u64 t; cvta.to.shared.u64 t, %1; cvt.u32.u64 %0, t; }" : "=r"(a) : "l"(p));
    return a;
}
__device__ __forceinline__ float ftanh(float x) {
    float y;
    asm("tanh.approx.f32 %0, %1;" : "=f"(y) : "f"(x));
    return y;
}
__device__ __forceinline__ float fsigm(float x) { return 0.5f * ftanh(0.5f * x) + 0.5f; }

__device__ __forceinline__ void ldsm4(uint32_t* r, uint32_t addr) {
    asm volatile("ldmatrix.sync.aligned.m8n8.x4.shared.b16 {%0,%1,%2,%3}, [%4];"
                 : "=r"(r[0]), "=r"(r[1]), "=r"(r[2]), "=r"(r[3]) : "r"(addr));
}
__device__ __forceinline__ void ldsm4t(uint32_t* r, uint32_t addr) {
    asm volatile("ldmatrix.sync.aligned.m8n8.x4.trans.shared.b16 {%0,%1,%2,%3}, [%4];"
                 : "=r"(r[0]), "=r"(r[1]), "=r"(r[2]), "=r"(r[3]) : "r"(addr));
}
__device__ __forceinline__ void mma16816(float* d, const uint32_t* a, uint32_t b0, uint32_t b1) {
    asm volatile(
        "mma.sync.aligned.m16n8k16.row.col.f32.bf16.bf16.f32 "
        "{%0,%1,%2,%3}, {%4,%5,%6,%7}, {%8,%9}, {%0,%1,%2,%3};"
        : "+f"(d[0]), "+f"(d[1]), "+f"(d[2]), "+f"(d[3])
        : "r"(a[0]), "r"(a[1]), "r"(a[2]), "r"(a[3]), "r"(b0), "r"(b1));
}
__device__ __forceinline__ void cp16(uint32_t dst, const void* src) {
    asm volatile("cp.async.cg.shared.global [%0], [%1], 16;" :: "r"(dst), "l"(src));
}
#define CP_COMMIT() asm volatile("cp.async.commit_group;" ::: "memory")
#define CP_WAIT(n)  asm volatile("cp.async.wait_group %0;" :: "n"(n) : "memory")

// ======= fused LSTM step: col-major state, K-major A smem + ldsm.trans, resident B ======
// 256 threads, 8 warps 4(M)x2(N), warp tile 32x64, CTA tile 128x128.
template <int KX, int HID, int BK>
__device__ __forceinline__ void lstm_body(int t, int m0, int n0, char* smemc) {
    constexpr int K = KX + HID;
    constexpr int SROW = 136;                // A smem: elems per k-row (272B, conflict-free)
    constexpr int STG_A = BK * SROW * 2;
    constexpr int SB = 2 * K + 8;            // B row length in halfs
    constexpr int CPT = K / BK;
    constexpr int NCH = 2 * CPT;             // hi chunks then lo chunks
    constexpr int GB = 2 * K / 8;
    const int tid = threadIdx.x;
    const int lane = tid & 31, wid = tid >> 5;
    const int wm = wid & 3, wn = wid >> 2;   // 4 x 2
    const uint32_t sbase = smem_u32(smemc);
    const uint32_t Bbase = sbase + 2 * STG_A;
    const int p = t & 1;

    const __nv_bfloat16 *xhi, *xlo, *hhi, *hlo;
    __nv_bfloat16 *hdhi, *hdlo;
    float* cbuf;
    const __nv_bfloat16* W;
    const float* bias;
    int xoff;
    if (HID == H1) {
        xhi = g_acthi; xlo = g_actlo; xoff = t * FEAT;
        hhi = g_h1hi[p]; hlo = g_h1lo[p];
        hdhi = g_h1hi[p ^ 1]; hdlo = g_h1lo[p ^ 1];
        cbuf = g_c1; W = g_Wp1; bias = g_bc1;
    } else {
        xhi = g_h1hi[p ^ 1]; xlo = g_h1lo[p ^ 1]; xoff = 0;
        hhi = g_h2hi[p]; hlo = g_h2lo[p];
        hdhi = g_h2hi[p ^ 1]; hdlo = g_h2lo[p ^ 1];
        cbuf = g_c2; W = g_Wp2; bias = g_bc2;
    }

    // A loader: per k-column, 16x 16B contiguous copies from col-major state
    auto load_a = [&](int c) {
        const bool hi = c < CPT;
        const int kbase = (hi ? c : c - CPT) * BK;
        const __nv_bfloat16* xa = hi ? xhi : xlo;
        const __nv_bfloat16* ha = hi ? hhi : hlo;
        const uint32_t As = sbase + (uint32_t)(c & 1) * STG_A;
#pragma unroll
        for (int task = tid; task < BK * 16; task += 256) {
            const int k = task >> 4, mg = task & 15;
            const int col = kbase + k;
            const __nv_bfloat16* src = (col < KX)
                ? xa + (size_t)(xoff + col) * BATCH + m0 + mg * 8
                : ha + (size_t)(col - KX) * BATCH + m0 + mg * 8;
            cp16(As + (uint32_t)(k * SROW + mg * 8) * 2, src);
        }
    };

    // prologue: resident B + first A chunk
#pragma unroll
    for (int task = tid; task < 128 * GB; task += 256) {
        const int n = task / GB, gg = task % GB;
        cp16(Bbase + (uint32_t)(n * SB + gg * 8) * 2,
             W + (size_t)(n0 + n) * (2 * K) + gg * 8);
    }
    load_a(0);
    CP_COMMIT();

    // ldsm.trans lane addressing for A (K-major smem):
    // lanes0-7 -> (k0-7, m0-7)=a0; 8-15 -> m+8 = a1; 16-23 -> k+8 = a2; 24-31 = a3
    const uint32_t arow = (uint32_t)((lane & 7) + ((lane >> 4) << 3));
    const uint32_t acol = (uint32_t)(wm * 32 + (((lane >> 3) & 1) << 3));
    const uint32_t brow = (uint32_t)(wn * 64 + ((lane >> 4) << 3) + (lane & 7));
    const uint32_t bcol8 = (uint32_t)(((lane >> 3) & 1) << 3);
    float acc[2][8][4] = {};

#pragma unroll 1
    for (int c = 0; c < NCH; c++) {
        CP_WAIT(0);
        __syncthreads();
        if (c + 1 < NCH) { load_a(c + 1); CP_COMMIT(); }
        const bool hi = c < CPT;
        const int kbase = (hi ? c : c - CPT) * BK;
        const uint32_t As = sbase + (uint32_t)(c & 1) * STG_A;
#pragma unroll
        for (int kk = 0; kk < BK / 16; kk++) {
            uint32_t a0[4], a1[4];
            ldsm4t(a0, As + ((kk * 16 + arow) * SROW + acol) * 2);
            ldsm4t(a1, As + ((kk * 16 + arow) * SROW + acol + 16) * 2);
            const int nsets = hi ? 2 : 1;
#pragma unroll
            for (int set = 0; set < 2; set++) {
                if (set >= nsets) break;
                const uint32_t cofs = (uint32_t)(kbase + kk * 16 + (set ? K : 0)) + bcol8;
                uint32_t b[4][4];
#pragma unroll
                for (int nj = 0; nj < 4; nj++)
                    ldsm4(b[nj], Bbase + ((brow + nj * 16) * SB + cofs) * 2);
#pragma unroll
                for (int mi = 0; mi < 2; mi++) {
                    const uint32_t* A = mi ? a1 : a0;
#pragma unroll
                    for (int nj = 0; nj < 4; nj++) {
                        mma16816(acc[mi][2 * nj], A, b[nj][0], b[nj][1]);
                        mma16816(acc[mi][2 * nj + 1], A, b[nj][2], b[nj][3]);
                    }
                }
            }
        }
    }

    // epilogue: pair-swap gates; col-major state -> coalesced stores
    const int g = lane >> 2;
    const bool odd = lane & 1;
#pragma unroll
    for (int ni = 0; ni < 8; ni++) {
        const int u = ((n0 + wn * 64 + ni * 8) >> 2) + ((lane & 2) >> 1);
        const float4 bb = *(const float4*)(bias + 4 * u);
#pragma unroll
        for (int mi = 0; mi < 2; mi++) {
            const float d0 = acc[mi][ni][0], d1 = acc[mi][ni][1];
            const float d2 = acc[mi][ni][2], d3 = acc[mi][ni][3];
            const float s0 = __shfl_xor_sync(0xffffffffu, odd ? d0 : d2, 1);
            const float s1 = __shfl_xor_sync(0xffffffffu, odd ? d1 : d3, 1);
            const float zi = (odd ? s0 : d0) + bb.x;
            const float zf = (odd ? s1 : d1) + bb.y;
            const float zg = (odd ? d2 : s0) + bb.z;
            const float zo = (odd ? d3 : s1) + bb.w;
            const int row = m0 + wm * 32 + mi * 16 + g + (odd ? 8 : 0);
            const float ig = fsigm(zi);
            const float fg = fsigm(zf);
            const float gg = ftanh(zg);
            const float og = fsigm(zo);
            const size_t off = (size_t)u * BATCH + row;   // col-major
            const float cn = fg * cbuf[off] + ig * gg;
            cbuf[off] = cn;
            const float hv = og * ftanh(cn);
            const __nv_bfloat16 hh = __float2bfloat16(hv);
            hdhi[off] = hh;
            hdlo[off] = __float2bfloat16(hv - __bfloat162float(hh));
        }
    }
}

__global__ __launch_bounds__(256, 2) void lstm1_first_kernel() {
    extern __shared__ char smem[];
    lstm_body<FEAT, H1, 48>(0, (blockIdx.x & 255) * 128, (blockIdx.x >> 8) * 128, smem);
}

// combined: lstm2(t) on blocks [0,256); lstm1(t+1) on blocks [256,1280)
__global__ __launch_bounds__(256, 2) void step_kernel(int t, int do_l1) {
    extern __shared__ char smem[];
    if (blockIdx.x < 256) {
        lstm_body<H1, H2, 32>(t, blockIdx.x * 128, 0, smem);
    } else if (do_l1) {
        const int bx = blockIdx.x - 256;
        lstm_body<FEAT, H1, 48>(t + 1, (bx & 255) * 128, (bx >> 8) * 128, smem);
    }
}

// ---------------- init & prepack ----------------
__global__ void init_state_kernel() {
    int idx = blockIdx.x * blockDim.x + threadIdx.x;
    int stride = gridDim.x * blockDim.x;
    const __nv_bfloat16 z = __float2bfloat16(0.f);
    for (int i = idx; i < BATCH * H1; i += stride) {
        g_h1hi[0][i] = z; g_h1lo[0][i] = z; g_c1[i] = 0.f;
    }
    for (int i = idx; i < BATCH * H2; i += stride) {
        g_h2hi[0][i] = z; g_h2lo[0][i] = z; g_c2[i] = 0.f;
    }
}

__global__ void prepack_kernel(const float* __restrict__ Wx1, const float* __restrict__ Wh1,
                               const float* __restrict__ b1,
                               const float* __restrict__ Wx2, const float* __restrict__ Wh2,
                               const float* __restrict__ b2,
                               const float* __restrict__ W_d1, const float* __restrict__ b_d1,
                               const float* __restrict__ gamma, const float* __restrict__ beta,
                               const float* __restrict__ mean, const float* __restrict__ var) {
    int idx = blockIdx.x * blockDim.x + threadIdx.x;
    int stride = gridDim.x * blockDim.x;
    {
        constexpr int K = FEAT + H1;
        for (int i = idx; i < 4 * H1 * K; i += stride) {
            int n = i / K, k = i % K;
            int u = n >> 2, g = n & 3, src = g * H1 + u;
            float w = (k < FEAT) ? Wx1[k * 4 * H1 + src] : Wh1[(k - FEAT) * 4 * H1 + src];
            __nv_bfloat16 hi = __float2bfloat16(w);
            g_Wp1[(size_t)n * 2 * K + k] = hi;
            g_Wp1[(size_t)n * 2 * K + K + k] = __float2bfloat16(w - __bfloat162float(hi));
        }
        for (int i = idx; i < 4 * H1; i += stride) {
            int u = i >> 2, g = i & 3;
            g_bc1[i] = b1[g * H1 + u];
        }
    }
    {
        constexpr int K = H1 + H2;
        for (int i = idx; i < 4 * H2 * K; i += stride) {
            int n = i / K, k = i % K;
            int u = n >> 2, g = n & 3, src = g * H2 + u;
            float w = (k < H1) ? Wx2[k * 4 * H2 + src] : Wh2[(k - H1) * 4 * H2 + src];
            __nv_bfloat16 hi = __float2bfloat16(w);
            g_Wp2[(size_t)n * 2 * K + k] = hi;
            g_Wp2[(size_t)n * 2 * K + K + k] = __float2bfloat16(w - __bfloat162float(hi));
        }
        for (int i = idx; i < 4 * H2; i += stride) {
            int u = i >> 2, g = i & 3;
            g_bc2[i] = b2[g * H2 + u];
        }
    }
    // Dense1 weights: panel-major [n][p*256 + {hi 0..127 | lo 128..255}], p = k>>7
    for (int i = idx; i < D_DENSE * D_IN; i += stride) {
        int n = i / D_IN, k = i % D_IN;
        int p = k >> 7, kk = k & 127;
        float w = W_d1[(size_t)k * D_DENSE + n];
        __nv_bfloat16 hi = __float2bfloat16(w);
        g_WpD[(size_t)n * 1024 + p * 256 + kk] = hi;
        g_WpD[(size_t)n * 1024 + p * 256 + 128 + kk] = __float2bfloat16(w - __bfloat162float(hi));
    }
    for (int i = idx; i < D_DENSE; i += stride) {
        float sc = gamma[i] * rsqrtf(var[i] + 1e-3f);
        g_d1sc[i] = sc;
        g_d1sh[i] = beta[i] + (b_d1[i] - mean[i]) * sc;
    }
}

// ---------------- Dense1 (verified engine), act written col-major ----------------
template <int K, int S>
__device__ __forceinline__ void warp_gemm3(uint32_t Asm, uint32_t Bsm,
                                           int wm, int wn, int lane, float acc[2][8][4]) {
    const uint32_t abase = Asm + ((((uint32_t)(wm * 32 + (lane & 15))) * S + ((lane >> 4) << 3)) << 1);
    const uint32_t bbase = Bsm + ((((uint32_t)(wn * 64 + ((lane >> 4) << 3) + (lane & 7))) * S
                                   + (((lane >> 3) & 1) << 3)) << 1);
#pragma unroll
    for (int term = 0; term < 3; term++) {
        const int ao = (term == 1) ? K : 0;
        const int bo = (term == 2) ? K : 0;
#pragma unroll
        for (int c = 0; c < K / 16; c++) {
            uint32_t a0[4], a1[4], b[4][4];
            ldsm4(a0, abase + ((ao + c * 16) << 1));
            ldsm4(a1, abase + ((16 * S + ao + c * 16) << 1));
#pragma unroll
            for (int nj = 0; nj < 4; nj++)
                ldsm4(b[nj], bbase + (((nj * 16) * S + bo + c * 16) << 1));
#pragma unroll
            for (int mi = 0; mi < 2; mi++) {
                const uint32_t* A = mi ? a1 : a0;
#pragma unroll
                for (int nj = 0; nj < 4; nj++) {
                    mma16816(acc[mi][2 * nj], A, b[nj][0], b[nj][1]);
                    mma16816(acc[mi][2 * nj + 1], A, b[nj][2], b[nj][3]);
                }
            }
        }
    }
}

__global__ __launch_bounds__(256, 1) void dense1_kernel(const float* __restrict__ x) {
    constexpr int KP = 128;
    constexpr int S = 2 * KP + 8;    // 264
    extern __shared__ char smem[];
    const uint32_t Asm = smem_u32(smem);
    const uint32_t Bsm = Asm + 128 * S * 2;
    char* const Bc = smem + 128 * S * 2;
    const int tid = threadIdx.x;
    const int lane = tid & 31, wid = tid >> 5;
    const int wm = wid & 3, wn = wid >> 2;
    const int m0 = blockIdx.x * 128, n0 = blockIdx.y * 128;

    float acc[2][8][4] = {};
    for (int p = 0; p < 4; p++) {
        for (int task = tid; task < 128 * 16; task += 256) {
            const int r = task >> 4, o = task & 15;
            const float* src = x + (size_t)(m0 + r) * D_IN + p * KP + o * 8;
            const float4 v0 = *(const float4*)src;
            const float4 v1 = *(const float4*)(src + 4);
            __nv_bfloat16 h[8], l[8];
            const float vv[8] = {v0.x, v0.y, v0.z, v0.w, v1.x, v1.y, v1.z, v1.w};
#pragma unroll
            for (int i = 0; i < 8; i++) {
                h[i] = __float2bfloat16(vv[i]);
                l[i] = __float2bfloat16(vv[i] - __bfloat162float(h[i]));
            }
            *(uint4*)(smem + ((size_t)r * S + o * 8) * 2) = *(uint4*)h;
            *(uint4*)(smem + ((size_t)r * S + KP + o * 8) * 2) = *(uint4*)l;
        }
        for (int task = tid; task < 128 * 32; task += 256) {
            const int n = task >> 5, o = task & 31;
            const uint4 v = *(const uint4*)(g_WpD + (size_t)(n0 + n) * 1024 + p * 256 + o * 8);
            *(uint4*)(Bc + ((size_t)n * S + o * 8) * 2) = v;
        }
        __syncthreads();
        warp_gemm3<KP, S>(Asm, Bsm, wm, wn, lane, acc);
        __syncthreads();
    }

    const int g = lane >> 2;
#pragma unroll
    for (int ni = 0; ni < 8; ni++) {
        const int n = n0 + wn * 64 + ni * 8 + (lane & 3) * 2;
        const float sc0 = g_d1sc[n], sc1 = g_d1sc[n + 1];
        const float sh0 = g_d1sh[n], sh1 = g_d1sh[n + 1];
#pragma unroll
        for (int mi = 0; mi < 2; mi++) {
#pragma unroll
            for (int half = 0; half < 2; half++) {
                const int row = m0 + wm * 32 + mi * 16 + g + half * 8;
                float v0 = acc[mi][ni][half * 2 + 0] * sc0 + sh0;
                float v1 = acc[mi][ni][half * 2 + 1] * sc1 + sh1;
                v0 = (v0 >= 0.f) ? v0 : 0.2f * v0;
                v1 = (v1 >= 0.f) ? v1 : 0.2f * v1;
                __nv_bfloat16 h0 = __float2bfloat16(v0), h1 = __float2bfloat16(v1);
                // col-major act
                g_acthi[(size_t)n * BATCH + row] = h0;
                g_acthi[(size_t)(n + 1) * BATCH + row] = h1;
                g_actlo[(size_t)n * BATCH + row] = __float2bfloat16(v0 - __bfloat162float(h0));
                g_actlo[(size_t)(n + 1) * BATCH + row] = __float2bfloat16(v1 - __bfloat162float(h1));
            }
        }
    }
}

// ---------------- Dense2 + softmax (col-major h2) ----------------
__global__ __launch_bounds__(256) void dense2_softmax_kernel(
    const float* __restrict__ Wd2, const float* __restrict__ bd2, float* __restrict__ out) {
    __shared__ float Ws[H2 * NCLS];
    __shared__ float bs[NCLS];
    int tid = threadIdx.x;
    for (int i = tid; i < H2 * NCLS; i += blockDim.x) Ws[i] = Wd2[i];
    if (tid < NCLS) bs[tid] = bd2[tid];
    __syncthreads();
    int row = blockIdx.x * blockDim.x + tid;
    const __nv_bfloat16* hh = g_h2hi[0];  // t=15 writes buffer 0
    const __nv_bfloat16* hl = g_h2lo[0];
    float acc[NCLS];
#pragma unroll
    for (int j = 0; j < NCLS; j++) acc[j] = bs[j];
#pragma unroll
    for (int k = 0; k < H2; k++) {
        float xv = __bfloat162float(hh[(size_t)k * BATCH + row])
                 + __bfloat162float(hl[(size_t)k * BATCH + row]);
#pragma unroll
        for (int j = 0; j < NCLS; j++) acc[j] += xv * Ws[k * NCLS + j];
    }
    float m = acc[0];
#pragma unroll
    for (int j = 1; j < NCLS; j++) m = fmaxf(m, acc[j]);
    float ssum = 0.f;
#pragma unroll
    for (int j = 0; j < NCLS; j++) { acc[j] = expf(acc[j] - m); ssum += acc[j]; }
    float inv = 1.f / ssum;
#pragma unroll
    for (int j = 0; j < NCLS; j++) out[(size_t)row * NCLS + j] = acc[j] * inv;
}

// ---------------- launch ----------------
extern "C" void kernel_launch(void* const* d_in, const int* in_sizes, int n_in,
                              void* d_out, int out_size) {
    const float* x        = (const float*)d_in[0];
    const float* W_d1     = (const float*)d_in[1];
    const float* b_d1     = (const float*)d_in[2];
    const float* bn_gamma = (const float*)d_in[3];
    const float* bn_beta  = (const float*)d_in[4];
    const float* bn_mean  = (const float*)d_in[5];
    const float* bn_var   = (const float*)d_in[6];
    const float* Wx1      = (const float*)d_in[7];
    const float* Wh1      = (const float*)d_in[8];
    const float* b1       = (const float*)d_in[9];
    const float* Wx2      = (const float*)d_in[10];
    const float* Wh2      = (const float*)d_in[11];
    const float* b2       = (const float*)d_in[12];
    const float* W_d2     = (const float*)d_in[13];
    const float* b_d2     = (const float*)d_in[14];
    float* out = (float*)d_out;

    // LSTM1: 2*48*136*2 + 128*296*2 = 26112 + 75776 = 101888
    // LSTM2: 2*32*136*2 + 128*328*2 = 17408 + 83968 = 101376
    const int SM_STEP = 101888;
    const int SMD     = 2 * 128 * (2 * 128 + 8) * 2;     // 135168

    cudaFuncSetAttribute(dense1_kernel, cudaFuncAttributeMaxDynamicSharedMemorySize, SMD);
    cudaFuncSetAttribute(lstm1_first_kernel, cudaFuncAttributeMaxDynamicSharedMemorySize, SM_STEP);
    cudaFuncSetAttribute(step_kernel, cudaFuncAttributeMaxDynamicSharedMemorySize, SM_STEP);

    prepack_kernel<<<256, 256>>>(Wx1, Wh1, b1, Wx2, Wh2, b2, W_d1, b_d1,
                                 bn_gamma, bn_beta, bn_mean, bn_var);
    init_state_kernel<<<2048, 256>>>();
    dense1_kernel<<<dim3(BATCH / 128, D_DENSE / 128), 256, SMD>>>(x);
    lstm1_first_kernel<<<1024, 256, SM_STEP>>>();
    for (int t = 0; t < TSTEPS; t++) {
        step_kernel<<<1280, 256, SM_STEP>>>(t, (t < TSTEPS - 1) ? 1 : 0);
    }
    dense2_softmax_kernel<<<BATCH / 256, 256>>>(W_d2, b_d2, out);
}